// round 14
// baseline (speedup 1.0000x reference)
#include <cuda_runtime.h>
#include <cuda_bf16.h>
#include <cuda_fp16.h>
#include <cstdint>
#include <math.h>

// ---------------------------------------------------------------------------
// Problem constants: B=4, T=1024, C=1024, H=16, D=64, F=4096, M=B*T=4096
// ---------------------------------------------------------------------------
#define M_ROWS 4096
#define C_DIM  1024
#define T_SEQ  1024
#define H_HEADS 16
#define F_DIM  4096
#define L2E 1.4426950408889634f

// ---------------------------------------------------------------------------
// Scratch (device globals)
// ---------------------------------------------------------------------------
__device__ float g_x1 [M_ROWS * C_DIM];
__device__ float g_x2 [M_ROWS * C_DIM];

__device__ __half g_h2   [M_ROWS * C_DIM];
__device__ __half g_attn2[M_ROWS * C_DIM];
__device__ __half g_ctx2 [M_ROWS * C_DIM];
__device__ __half g_ffn2a[(size_t)M_ROWS * F_DIM];

__device__ __half w_qkv2[C_DIM * 3 * C_DIM];
__device__ __half w_ao2 [C_DIM * C_DIM];
__device__ __half w_q2  [C_DIM * C_DIM];
__device__ __half w_kv2 [C_DIM * 2 * C_DIM];
__device__ __half w_co2 [C_DIM * C_DIM];
__device__ __half w_f1_2[C_DIM * F_DIM];
__device__ __half w_f2_2[(size_t)F_DIM * C_DIM];

#define ATT_ELEMS (4 * H_HEADS * T_SEQ * 64)
__device__ __half a_qh [ATT_ELEMS];
__device__ __half a_kh [ATT_ELEMS];     // self-attention K
__device__ __half a_vh [ATT_ELEMS];     // self-attention V
__device__ __half a_kh2[ATT_ELEMS];     // cross-attention K (separate: no WAR vs fmha_self)
__device__ __half a_vh2[ATT_ELEMS];     // cross-attention V

// ---------------------------------------------------------------------------
// Helpers
// ---------------------------------------------------------------------------
__device__ __forceinline__ void cp16(uint32_t dst, const void* src) {
    asm volatile("cp.async.cg.shared.global [%0], [%1], 16;\n" :: "r"(dst), "l"(src));
}
__device__ __forceinline__ void ldm_x4(uint32_t& r0, uint32_t& r1, uint32_t& r2,
                                       uint32_t& r3, uint32_t addr) {
    asm volatile("ldmatrix.sync.aligned.m8n8.x4.shared.b16 {%0,%1,%2,%3}, [%4];\n"
        : "=r"(r0), "=r"(r1), "=r"(r2), "=r"(r3) : "r"(addr));
}
__device__ __forceinline__ void ldm_x4_t(uint32_t& r0, uint32_t& r1, uint32_t& r2,
                                         uint32_t& r3, uint32_t addr) {
    asm volatile("ldmatrix.sync.aligned.m8n8.x4.trans.shared.b16 {%0,%1,%2,%3}, [%4];\n"
        : "=r"(r0), "=r"(r1), "=r"(r2), "=r"(r3) : "r"(addr));
}
__device__ __forceinline__ void ldm_x2_t(uint32_t& r0, uint32_t& r1, uint32_t addr) {
    asm volatile("ldmatrix.sync.aligned.m8n8.x2.trans.shared.b16 {%0,%1}, [%2];\n"
        : "=r"(r0), "=r"(r1) : "r"(addr));
}
__device__ __forceinline__ void mma_f16(float* d, const uint32_t* a, const uint32_t* b) {
    asm volatile("mma.sync.aligned.m16n8k16.row.col.f32.f16.f16.f32 "
        "{%0,%1,%2,%3}, {%4,%5,%6,%7}, {%8,%9}, {%0,%1,%2,%3};\n"
        : "+f"(d[0]), "+f"(d[1]), "+f"(d[2]), "+f"(d[3])
        : "r"(a[0]), "r"(a[1]), "r"(a[2]), "r"(a[3]), "r"(b[0]), "r"(b[1]));
}
__device__ __forceinline__ uint32_t ex2_f16x2(float a, float b) {
    __half2 h = __floats2half2_rn(a, b);
    uint32_t u = *reinterpret_cast<uint32_t*>(&h);
    uint32_t r;
    asm volatile("ex2.approx.f16x2 %0, %1;\n" : "=r"(r) : "r"(u));
    return r;
}

// ---------------------------------------------------------------------------
// Vectorized conversion: fp32 -> f16, 8 elems/thread
// ---------------------------------------------------------------------------
__global__ void convB_kernel(const float* __restrict__ src, __half* __restrict__ dst,
                             int total8) {
    int e = blockIdx.x * 256 + threadIdx.x;
    if (e >= total8) return;
    const float4* s = (const float4*)src + 2 * (size_t)e;
    float4 a = s[0], b = s[1];
    __half2 h0 = __floats2half2_rn(a.x, a.y);
    __half2 h1 = __floats2half2_rn(a.z, a.w);
    __half2 h2 = __floats2half2_rn(b.x, b.y);
    __half2 h3 = __floats2half2_rn(b.z, b.w);
    uint4 pk = make_uint4(*(uint32_t*)&h0, *(uint32_t*)&h1,
                          *(uint32_t*)&h2, *(uint32_t*)&h3);
    ((uint4*)dst)[e] = pk;
}

// ---------------------------------------------------------------------------
// LayerNorm (writes f16)
// ---------------------------------------------------------------------------
__global__ void __launch_bounds__(256) ln_kernel(
    const float* __restrict__ x, const float* __restrict__ g,
    const float* __restrict__ b, __half* __restrict__ out)
{
    int row = blockIdx.x;
    int tid = threadIdx.x;
    float4 v = ((const float4*)(x + (size_t)row * C_DIM))[tid];
    float s  = v.x + v.y + v.z + v.w;
    float s2 = v.x*v.x + v.y*v.y + v.z*v.z + v.w*v.w;
    __shared__ float red[64];
    #pragma unroll
    for (int o = 16; o; o >>= 1) {
        s  += __shfl_xor_sync(0xffffffffu, s,  o);
        s2 += __shfl_xor_sync(0xffffffffu, s2, o);
    }
    int warp = tid >> 5;
    if ((tid & 31) == 0) { red[warp] = s; red[32 + warp] = s2; }
    __syncthreads();
    if (tid < 32) {
        s  = (tid < 8) ? red[tid]      : 0.f;
        s2 = (tid < 8) ? red[32 + tid] : 0.f;
        #pragma unroll
        for (int o = 4; o; o >>= 1) {
            s  += __shfl_xor_sync(0xffffffffu, s,  o);
            s2 += __shfl_xor_sync(0xffffffffu, s2, o);
        }
        if (tid == 0) { red[0] = s; red[32] = s2; }
    }
    __syncthreads();
    float mean = red[0]  * (1.0f / C_DIM);
    float var  = red[32] * (1.0f / C_DIM) - mean * mean;
    float inv  = rsqrtf(var + 1e-5f);
    float4 gv = ((const float4*)g)[tid];
    float4 bv = ((const float4*)b)[tid];
    __half2 o0 = __floats2half2_rn((v.x - mean) * inv * gv.x + bv.x,
                                   (v.y - mean) * inv * gv.y + bv.y);
    __half2 o1 = __floats2half2_rn((v.z - mean) * inv * gv.z + bv.z,
                                   (v.w - mean) * inv * gv.w + bv.w);
    uint2 pk = make_uint2(*(uint32_t*)&o0, *(uint32_t*)&o1);
    *(uint2*)(out + (size_t)row * C_DIM + 4 * tid) = pk;
}

// ---------------------------------------------------------------------------
// f16 tensor-core GEMM: 5-stage cp.async pipeline (94.7 KB smem, 2 CTAs/SM),
// BM=BN=128, BK=32, 128 threads (4 warps 2x2), warp tile 64x64, single sync.
// EPI: 1 = +bias+res (fp32 out)
//      3 = +bias, exact GELU, f16 out
//      4 = +bias, fused QKV attention-operand output
//      5 = +bias, q-only attention output (x0.125 -> f16)
//      6 = +bias, kv attention output (k | v)
// ---------------------------------------------------------------------------
#define BM 128
#define BN 128
#define BK 32
#define A_PAD 40
#define B_PAD 136
#define NSTAGE 5
#define BG_SMEM (NSTAGE * (BM * A_PAD + BK * B_PAD) * 2)   // 94720 B

template<int EPI>
__global__ void __launch_bounds__(128, 2) bgemm_kernel(
    const __half* __restrict__ A, const __half* __restrict__ Bm,
    const float* __restrict__ bias, const float* __restrict__ res,
    float* __restrict__ Cf, __half* __restrict__ Ct,
    __half* __restrict__ pq, __half* __restrict__ pkh,
    __half* __restrict__ pv,
    int M, int N, int Kp)
{
    extern __shared__ char sm_raw[];
    __half* As = (__half*)sm_raw;
    __half* Bs = (__half*)(sm_raw + NSTAGE * BM * A_PAD * sizeof(__half));

    const int tid  = threadIdx.x;
    const int lane = tid & 31, wid = tid >> 5;
    const int bm0 = blockIdx.y * BM, bn0 = blockIdx.x * BN;
    const int wm = (wid & 1) * 64, wn = (wid >> 1) * 64;

    float acc[4][8][4];
    #pragma unroll
    for (int i = 0; i < 4; i++)
        #pragma unroll
        for (int j = 0; j < 8; j++)
            #pragma unroll
            for (int r = 0; r < 4; r++) acc[i][j][r] = 0.f;

    auto As_u32 = [&](int s, int r, int c) -> uint32_t {
        return (uint32_t)__cvta_generic_to_shared(As + ((s * BM + r) * A_PAD + c));
    };
    auto Bs_u32 = [&](int s, int r, int c) -> uint32_t {
        return (uint32_t)__cvta_generic_to_shared(Bs + ((s * BK + r) * B_PAD + c));
    };

    auto load_stage = [&](int s, int k0) {
        #pragma unroll
        for (int i = 0; i < 4; i++) {
            int chunk = tid + i * 128;
            int ar = chunk >> 2, ac = (chunk & 3) * 8;
            cp16(As_u32(s, ar, ac), A + (size_t)(bm0 + ar) * Kp + k0 + ac);
            int br = chunk >> 4, bc = (chunk & 15) * 8;
            cp16(Bs_u32(s, br, bc), Bm + (size_t)(k0 + br) * N + bn0 + bc);
        }
        asm volatile("cp.async.commit_group;\n" ::);
    };

    const int NK = Kp / BK;
    load_stage(0, 0);
    load_stage(1, BK);
    load_stage(2, 2 * BK);
    load_stage(3, 3 * BK);

    int s = 0, sl = 4;   // current compute stage; next stage to fill
    for (int t = 0; t < NK; t++) {
        const int rem = NK - 1 - t;
        if (rem >= 3)      asm volatile("cp.async.wait_group 3;\n" ::);
        else if (rem == 2) asm volatile("cp.async.wait_group 2;\n" ::);
        else if (rem == 1) asm volatile("cp.async.wait_group 1;\n" ::);
        else               asm volatile("cp.async.wait_group 0;\n" ::);
        __syncthreads();
        if (t + 4 < NK) {
            load_stage(sl, (t + 4) * BK);
            if (++sl == NSTAGE) sl = 0;
        }

        #pragma unroll
        for (int k16 = 0; k16 < 2; k16++) {
            uint32_t af[4][4];
            #pragma unroll
            for (int mi = 0; mi < 4; mi++) {
                uint32_t addr = As_u32(s, wm + mi * 16 + (lane & 15),
                                       k16 * 16 + ((lane >> 4) << 3));
                ldm_x4(af[mi][0], af[mi][1], af[mi][2], af[mi][3], addr);
            }
            uint32_t bfr[8][2];
            #pragma unroll
            for (int njp = 0; njp < 4; njp++) {
                int kr = k16 * 16 + ((lane >> 3) & 1) * 8 + (lane & 7);
                int nc = wn + njp * 16 + ((lane >> 4) & 1) * 8;
                uint32_t r0, r1, r2, r3;
                ldm_x4_t(r0, r1, r2, r3, Bs_u32(s, kr, nc));
                bfr[2*njp][0] = r0; bfr[2*njp][1] = r1;
                bfr[2*njp+1][0] = r2; bfr[2*njp+1][1] = r3;
            }
            #pragma unroll
            for (int mi = 0; mi < 4; mi++)
                #pragma unroll
                for (int nj = 0; nj < 8; nj++)
                    mma_f16(acc[mi][nj], af[mi], bfr[nj]);
        }
        if (++s == NSTAGE) s = 0;
    }

    const int g = lane >> 2, tig = lane & 3;
    #pragma unroll
    for (int mi = 0; mi < 4; mi++) {
        #pragma unroll
        for (int r2 = 0; r2 < 2; r2++) {
            int row = bm0 + wm + mi * 16 + g + r2 * 8;
            #pragma unroll
            for (int nj = 0; nj < 8; nj++) {
                int col = bn0 + wn + nj * 8 + tig * 2;
                float v0 = acc[mi][nj][r2 * 2 + 0] + bias[col];
                float v1 = acc[mi][nj][r2 * 2 + 1] + bias[col + 1];
                if (EPI == 1) {
                    float2 rv = *(const float2*)(res + (size_t)row * N + col);
                    v0 += rv.x; v1 += rv.y;
                    *(float2*)(Cf + (size_t)row * N + col) = make_float2(v0, v1);
                }
                if (EPI == 3) {
                    v0 = 0.5f * v0 * (1.0f + erff(v0 * 0.7071067811865475f));
                    v1 = 0.5f * v1 * (1.0f + erff(v1 * 0.7071067811865475f));
                    *(__half2*)(Ct + (size_t)row * N + col) = __floats2half2_rn(v0, v1);
                }
                if (EPI >= 4) {
                    int kind = (EPI == 5) ? 0
                             : (EPI == 4) ? (col >> 10)
                             : ((col >> 10) + 1);
                    int cc = (EPI == 5) ? col : (col & 1023);
                    int hh = cc >> 6, dd = cc & 63;
                    int b_ = row >> 10, t_ = row & 1023;
                    size_t oidx = ((size_t)((b_ * 16 + hh) * 1024) + t_) * 64 + dd;
                    if (kind == 0) {
                        *(__half2*)(pq + oidx) =
                            __floats2half2_rn(v0 * 0.125f, v1 * 0.125f);
                    } else if (kind == 1) {
                        *(__half2*)(pkh + oidx) = __floats2half2_rn(v0, v1);
                    } else {
                        *(__half2*)(pv + oidx) = __floats2half2_rn(v0, v1);
                    }
                }
            }
        }
    }
}

// ---------------------------------------------------------------------------
// Tensor-core flash attention v3 (R10/R11-proven)
// ---------------------------------------------------------------------------
#define FD 72
#define FTILE (64 * FD)
#define FMHA_SMEM (5 * FTILE * 2)

template<bool CAUSAL>
__global__ void __launch_bounds__(128) fmha_kernel(
    const __half* __restrict__ Qh_, const __half* __restrict__ Kh_,
    const __half* __restrict__ Vh_, __half* __restrict__ Op)
{
    const int qt = CAUSAL ? (gridDim.x - 1 - (int)blockIdx.x) : blockIdx.x;
    const int h = blockIdx.y, b = blockIdx.z;
    const int bh = b * H_HEADS + h;
    const int tid = threadIdx.x;
    const int lane = tid & 31, wid = tid >> 5;

    extern __shared__ __half sm[];
    __half* sQ = sm;
    auto sK = [&](int s) { return sm + FTILE + (s * 2) * FTILE; };
    auto sV = [&](int s) { return sm + FTILE + (s * 2 + 1) * FTILE; };

    const size_t qbase  = ((size_t)bh * T_SEQ + qt * 64) * 64;
    const size_t kvbase = (size_t)bh * T_SEQ * 64;

    const int ntiles = CAUSAL ? (qt + 1) : (T_SEQ / 64);

    for (int idx = tid; idx < 64 * 8; idx += 128) {
        int pos = idx >> 3, c = 64 + (idx & 7);
        sV(0)[pos * FD + c] = (c == 64) ? __float2half(1.0f) : __float2half(0.0f);
        sV(1)[pos * FD + c] = (c == 64) ? __float2half(1.0f) : __float2half(0.0f);
    }

    auto load_q = [&]() {
        #pragma unroll
        for (int i = 0; i < 4; i++) {
            int chunk = tid + i * 128;
            int r = chunk >> 3, c8 = (chunk & 7) * 8;
            cp16((uint32_t)__cvta_generic_to_shared(sQ + r * FD + c8), Qh_ + qbase + r * 64 + c8);
        }
    };
    auto load_kv = [&](int s, int kt) {
        #pragma unroll
        for (int i = 0; i < 4; i++) {
            int chunk = tid + i * 128;
            int r = chunk >> 3, c8 = (chunk & 7) * 8;
            size_t src = kvbase + (size_t)(kt * 64 + r) * 64 + c8;
            cp16((uint32_t)__cvta_generic_to_shared(sK(s) + r * FD + c8), Kh_ + src);
            cp16((uint32_t)__cvta_generic_to_shared(sV(s) + r * FD + c8), Vh_ + src);
        }
    };

    load_q();
    load_kv(0, 0);
    asm volatile("cp.async.commit_group;\n" ::);
    if (ntiles > 1) load_kv(1, 1);
    asm volatile("cp.async.commit_group;\n" ::);

    float oa[9][4];
    #pragma unroll
    for (int n = 0; n < 9; n++)
        #pragma unroll
        for (int r = 0; r < 4; r++) oa[n][r] = 0.f;
    float m0 = -1e30f, m1 = -1e30f;

    const int g = lane >> 2, tq = lane & 3;

    for (int kt = 0; kt < ntiles; kt++) {
        const int s = kt & 1;
        if (kt + 1 < ntiles) asm volatile("cp.async.wait_group 1;\n" ::);
        else                 asm volatile("cp.async.wait_group 0;\n" ::);
        __syncthreads();

        float sa[8][4];
        #pragma unroll
        for (int n = 0; n < 8; n++)
            #pragma unroll
            for (int r = 0; r < 4; r++) sa[n][r] = 0.f;

        {
            const __half* Kp = sK(s);
            #pragma unroll
            for (int kc = 0; kc < 4; kc++) {
                uint32_t a[4];
                ldm_x4(a[0], a[1], a[2], a[3],
                    (uint32_t)__cvta_generic_to_shared(
                        sQ + (wid * 16 + (lane & 15)) * FD + kc * 16 + ((lane >> 4) << 3)));
                #pragma unroll
                for (int njp = 0; njp < 4; njp++) {
                    uint32_t r0, r1, r2, r3;
                    ldm_x4(r0, r1, r2, r3,
                        (uint32_t)__cvta_generic_to_shared(
                            Kp + (njp * 16 + ((lane >> 4) & 1) * 8 + (lane & 7)) * FD
                               + kc * 16 + ((lane >> 3) & 1) * 8));
                    uint32_t b0[2] = { r0, r1 }, b1[2] = { r2, r3 };
                    mma_f16(sa[2*njp],   a, b0);
                    mma_f16(sa[2*njp+1], a, b1);
                }
            }
        }

        if (CAUSAL && kt == qt) {
            int q0l = wid * 16 + g;
            #pragma unroll
            for (int nj = 0; nj < 8; nj++) {
                int c0 = nj * 8 + 2 * tq;
                if (c0     > q0l)     sa[nj][0] = -1e30f;
                if (c0 + 1 > q0l)     sa[nj][1] = -1e30f;
                if (c0     > q0l + 8) sa[nj][2] = -1e30f;
                if (c0 + 1 > q0l + 8) sa[nj][3] = -1e30f;
            }
        }

        float mx0 = -1e30f, mx1 = -1e30f;
        #pragma unroll
        for (int nj = 0; nj < 8; nj++) {
            mx0 = fmaxf(mx0, fmaxf(sa[nj][0], sa[nj][1]));
            mx1 = fmaxf(mx1, fmaxf(sa[nj][2], sa[nj][3]));
        }
        #pragma unroll
        for (int o = 1; o <= 2; o <<= 1) {
            mx0 = fmaxf(mx0, __shfl_xor_sync(0xffffffffu, mx0, o));
            mx1 = fmaxf(mx1, __shfl_xor_sync(0xffffffffu, mx1, o));
        }
        float mn0 = fmaxf(m0, mx0), mn1 = fmaxf(m1, mx1);
        float tm0 = mn0 * L2E, tm1 = mn1 * L2E;
        float corr0 = exp2f(m0 * L2E - tm0);
        float corr1 = exp2f(m1 * L2E - tm1);
        m0 = mn0; m1 = mn1;
        #pragma unroll
        for (int n = 0; n < 9; n++) {
            oa[n][0] *= corr0; oa[n][1] *= corr0;
            oa[n][2] *= corr1; oa[n][3] *= corr1;
        }
        uint32_t pf[8][2];
        #pragma unroll
        for (int nj = 0; nj < 8; nj++) {
            pf[nj][0] = ex2_f16x2(fmaf(sa[nj][0], L2E, -tm0), fmaf(sa[nj][1], L2E, -tm0));
            pf[nj][1] = ex2_f16x2(fmaf(sa[nj][2], L2E, -tm1), fmaf(sa[nj][3], L2E, -tm1));
        }

        {
            const __half* Vt = sV(s);
            #pragma unroll
            for (int kc = 0; kc < 4; kc++) {
                uint32_t a[4] = { pf[2*kc][0], pf[2*kc][1], pf[2*kc+1][0], pf[2*kc+1][1] };
                #pragma unroll
                for (int njp = 0; njp < 4; njp++) {
                    uint32_t r0, r1, r2, r3;
                    ldm_x4_t(r0, r1, r2, r3,
                        (uint32_t)__cvta_generic_to_shared(
                            Vt + (kc * 16 + ((lane >> 3) & 1) * 8 + (lane & 7)) * FD
                               + njp * 16 + ((lane >> 4) & 1) * 8));
                    uint32_t b0[2] = { r0, r1 }, b1[2] = { r2, r3 };
                    mma_f16(oa[2*njp],   a, b0);
                    mma_f16(oa[2*njp+1], a, b1);
                }
                uint32_t r0, r1;
                ldm_x2_t(r0, r1,
                    (uint32_t)__cvta_generic_to_shared(
                        Vt + (kc * 16 + (lane & 15)) * FD + 64));
                uint32_t b2[2] = { r0, r1 };
                mma_f16(oa[8], a, b2);
            }
        }

        __syncthreads();
        if (kt + 2 < ntiles) load_kv(s, kt + 2);
        asm volatile("cp.async.commit_group;\n" ::);
    }

    float l0 = __shfl_sync(0xffffffffu, oa[8][0], lane & ~3);
    float l1 = __shfl_sync(0xffffffffu, oa[8][2], lane & ~3);
    float inv0 = 1.0f / l0, inv1 = 1.0f / l1;

    size_t r0 = (size_t)b * T_SEQ + qt * 64 + wid * 16 + g;
    size_t r1 = r0 + 8;
    #pragma unroll
    for (int nj = 0; nj < 8; nj++) {
        int col = h * 64 + nj * 8 + 2 * tq;
        *(__half2*)(Op + r0 * C_DIM + col) =
            __floats2half2_rn(oa[nj][0] * inv0, oa[nj][1] * inv0);
        *(__half2*)(Op + r1 * C_DIM + col) =
            __floats2half2_rn(oa[nj][2] * inv1, oa[nj][3] * inv1);
    }
}

// ---------------------------------------------------------------------------
// Launch: fork-join dual-stream schedule (graph-capturable).
// Stream B: conversions (hidden under qkv GEMM), then kv GEMM immediately
// (separate kh2/vh2 buffers -> no WAR vs fmha_self) overlapping fmha_self.
// ---------------------------------------------------------------------------
static inline int cdiv(int a, int b) { return (a + b - 1) / b; }

extern "C" void kernel_launch(void* const* d_in, const int* in_sizes, int n_in,
                              void* d_out, int out_size)
{
    const float* x           = (const float*)d_in[0];
    const float* context     = (const float*)d_in[1];
    const float* ln1_g       = (const float*)d_in[2];
    const float* ln1_b       = (const float*)d_in[3];
    const float* qkv_w       = (const float*)d_in[4];
    const float* qkv_b       = (const float*)d_in[5];
    const float* attn_out_w  = (const float*)d_in[6];
    const float* attn_out_b  = (const float*)d_in[7];
    const float* lnc_g       = (const float*)d_in[8];
    const float* lnc_b       = (const float*)d_in[9];
    const float* q_w         = (const float*)d_in[10];
    const float* q_b         = (const float*)d_in[11];
    const float* kv_w        = (const float*)d_in[12];
    const float* kv_b        = (const float*)d_in[13];
    const float* cross_out_w = (const float*)d_in[14];
    const float* cross_out_b = (const float*)d_in[15];
    const float* ln2_g       = (const float*)d_in[16];
    const float* ln2_b       = (const float*)d_in[17];
    const float* ffn_w1      = (const float*)d_in[18];
    const float* ffn_b1      = (const float*)d_in[19];
    const float* ffn_w2      = (const float*)d_in[20];
    const float* ffn_b2      = (const float*)d_in[21];
    float* out = (float*)d_out;

    float *x1, *x2;
    __half *h2, *attn2, *ctx2, *ffn2a;
    __half *wqkv2, *wao2, *wq2, *wkv2, *wco2, *wf1, *wf2;
    __half *qh, *kh, *vh, *kh2, *vh2;
    cudaGetSymbolAddress((void**)&x1,    g_x1);
    cudaGetSymbolAddress((void**)&x2,    g_x2);
    cudaGetSymbolAddress((void**)&h2,    g_h2);
    cudaGetSymbolAddress((void**)&attn2, g_attn2);
    cudaGetSymbolAddress((void**)&ctx2,  g_ctx2);
    cudaGetSymbolAddress((void**)&ffn2a, g_ffn2a);
    cudaGetSymbolAddress((void**)&wqkv2, w_qkv2);
    cudaGetSymbolAddress((void**)&wao2,  w_ao2);
    cudaGetSymbolAddress((void**)&wq2,   w_q2);
    cudaGetSymbolAddress((void**)&wkv2,  w_kv2);
    cudaGetSymbolAddress((void**)&wco2,  w_co2);
    cudaGetSymbolAddress((void**)&wf1,   w_f1_2);
    cudaGetSymbolAddress((void**)&wf2,   w_f2_2);
    cudaGetSymbolAddress((void**)&qh,  a_qh);
    cudaGetSymbolAddress((void**)&kh,  a_kh);
    cudaGetSymbolAddress((void**)&vh,  a_vh);
    cudaGetSymbolAddress((void**)&kh2, a_kh2);
    cudaGetSymbolAddress((void**)&vh2, a_vh2);

    cudaFuncSetAttribute(bgemm_kernel<1>, cudaFuncAttributeMaxDynamicSharedMemorySize, BG_SMEM);
    cudaFuncSetAttribute(bgemm_kernel<3>, cudaFuncAttributeMaxDynamicSharedMemorySize, BG_SMEM);
    cudaFuncSetAttribute(bgemm_kernel<4>, cudaFuncAttributeMaxDynamicSharedMemorySize, BG_SMEM);
    cudaFuncSetAttribute(bgemm_kernel<5>, cudaFuncAttributeMaxDynamicSharedMemorySize, BG_SMEM);
    cudaFuncSetAttribute(bgemm_kernel<6>, cudaFuncAttributeMaxDynamicSharedMemorySize, BG_SMEM);
    cudaFuncSetAttribute(fmha_kernel<true>,  cudaFuncAttributeMaxDynamicSharedMemorySize, FMHA_SMEM);
    cudaFuncSetAttribute(fmha_kernel<false>, cudaFuncAttributeMaxDynamicSharedMemorySize, FMHA_SMEM);

    const int M = M_ROWS, C = C_DIM, F = F_DIM;
    dim3 fgrid(T_SEQ / 64, H_HEADS, 4);

    // --- fork-join infrastructure (leaked; kernel_launch runs only ~3x) ---
    cudaStream_t sB;
    cudaStreamCreateWithFlags(&sB, cudaStreamNonBlocking);
    cudaEvent_t evFork, evWqkv, evConvs, evKV;
    cudaEventCreateWithFlags(&evFork,  cudaEventDisableTiming);
    cudaEventCreateWithFlags(&evWqkv,  cudaEventDisableTiming);
    cudaEventCreateWithFlags(&evConvs, cudaEventDisableTiming);
    cudaEventCreateWithFlags(&evKV,    cudaEventDisableTiming);

    // fork
    cudaEventRecord(evFork, 0);
    cudaStreamWaitEvent(sB, evFork, 0);

    // Stream B: conversions (wqkv first so the qkv GEMM can start ASAP)
    convB_kernel<<<cdiv(C * 3 * C / 8, 256), 256, 0, sB>>>(qkv_w, wqkv2, C * 3 * C / 8);
    cudaEventRecord(evWqkv, sB);
    convB_kernel<<<cdiv(C * 2 * C / 8, 256), 256, 0, sB>>>(kv_w,        wkv2, C * 2 * C / 8);
    convB_kernel<<<cdiv(M * C / 8,     256), 256, 0, sB>>>(context,     ctx2, M * C / 8);
    convB_kernel<<<cdiv(C * C / 8,     256), 256, 0, sB>>>(attn_out_w,  wao2, C * C / 8);
    convB_kernel<<<cdiv(C * C / 8,     256), 256, 0, sB>>>(q_w,         wq2,  C * C / 8);
    convB_kernel<<<cdiv(C * C / 8,     256), 256, 0, sB>>>(cross_out_w, wco2, C * C / 8);
    convB_kernel<<<cdiv(C * F / 8,     256), 256, 0, sB>>>(ffn_w1,      wf1,  C * F / 8);
    convB_kernel<<<cdiv(F * C / 8,     256), 256, 0, sB>>>(ffn_w2,      wf2,  F * C / 8);
    cudaEventRecord(evConvs, sB);

    // Stream B: kv GEMM (writes kh2/vh2 — independent of self-attention path);
    // overlaps fmha_self on stream A.
    bgemm_kernel<6><<<dim3(2 * C / BN, M / BM), 128, BG_SMEM, sB>>>(
        ctx2, wkv2, kv_b, nullptr, nullptr, nullptr,
        nullptr, kh2, vh2, M, 2 * C, C);
    cudaEventRecord(evKV, sB);

    // Stream A (default): LN1, qkv GEMM (after wqkv2), self-attention
    ln_kernel<<<M, 256>>>(x, ln1_g, ln1_b, h2);
    cudaStreamWaitEvent(0, evWqkv, 0);
    bgemm_kernel<4><<<dim3(3 * C / BN, M / BM), 128, BG_SMEM>>>(
        h2, wqkv2, qkv_b, nullptr, nullptr, nullptr,
        qh, kh, vh, M, 3 * C, C);
    fmha_kernel<true><<<fgrid, 128, FMHA_SMEM>>>(qh, kh, vh, attn2);

    // Stream A: attn_out (needs wao2 -> evConvs), LNc, q GEMM
    cudaStreamWaitEvent(0, evConvs, 0);
    bgemm_kernel<1><<<dim3(C / BN, M / BM), 128, BG_SMEM>>>(
        attn2, wao2, attn_out_b, x, x1, nullptr,
        nullptr, nullptr, nullptr, M, C, C);
    ln_kernel<<<M, 256>>>(x1, lnc_g, lnc_b, h2);
    bgemm_kernel<5><<<dim3(C / BN, M / BM), 128, BG_SMEM>>>(
        h2, wq2, q_b, nullptr, nullptr, nullptr,
        qh, nullptr, nullptr, M, C, C);

    // join: cross-attention needs kv GEMM output
    cudaStreamWaitEvent(0, evKV, 0);
    fmha_kernel<false><<<fgrid, 128, FMHA_SMEM>>>(qh, kh2, vh2, attn2);
    bgemm_kernel<1><<<dim3(C / BN, M / BM), 128, BG_SMEM>>>(
        attn2, wco2, cross_out_b, x1, x2, nullptr,
        nullptr, nullptr, nullptr, M, C, C);

    // FFN
    ln_kernel<<<M, 256>>>(x2, ln2_g, ln2_b, h2);
    bgemm_kernel<3><<<dim3(F / BN, M / BM), 128, BG_SMEM>>>(
        h2, wf1, ffn_b1, nullptr, nullptr, ffn2a,
        nullptr, nullptr, nullptr, M, F, C);
    bgemm_kernel<1><<<dim3(C / BN, M / BM), 128, BG_SMEM>>>(
        ffn2a, wf2, ffn_b2, x2, out, nullptr,
        nullptr, nullptr, nullptr, M, C, F);
}

// round 15
// speedup vs baseline: 1.0056x; 1.0056x over previous
#include <cuda_runtime.h>
#include <cuda_bf16.h>
#include <cuda_fp16.h>
#include <cstdint>
#include <math.h>

// ---------------------------------------------------------------------------
// Problem constants: B=4, T=1024, C=1024, H=16, D=64, F=4096, M=B*T=4096
// ---------------------------------------------------------------------------
#define M_ROWS 4096
#define C_DIM  1024
#define T_SEQ  1024
#define H_HEADS 16
#define F_DIM  4096
#define L2E 1.4426950408889634f

// ---------------------------------------------------------------------------
// Scratch (device globals)
// ---------------------------------------------------------------------------
__device__ float g_x1 [M_ROWS * C_DIM];
__device__ float g_x2 [M_ROWS * C_DIM];

__device__ __half g_h2   [M_ROWS * C_DIM];
__device__ __half g_attn2[M_ROWS * C_DIM];
__device__ __half g_ctx2 [M_ROWS * C_DIM];
__device__ __half g_ffn2a[(size_t)M_ROWS * F_DIM];

__device__ __half w_qkv2[C_DIM * 3 * C_DIM];
__device__ __half w_ao2 [C_DIM * C_DIM];
__device__ __half w_q2  [C_DIM * C_DIM];
__device__ __half w_kv2 [C_DIM * 2 * C_DIM];
__device__ __half w_co2 [C_DIM * C_DIM];
__device__ __half w_f1_2[C_DIM * F_DIM];
__device__ __half w_f2_2[(size_t)F_DIM * C_DIM];

#define ATT_ELEMS (4 * H_HEADS * T_SEQ * 64)
__device__ __half a_qh[ATT_ELEMS];
__device__ __half a_kh[ATT_ELEMS];
__device__ __half a_vh[ATT_ELEMS];

// ---------------------------------------------------------------------------
// Helpers
// ---------------------------------------------------------------------------
__device__ __forceinline__ void cp16(uint32_t dst, const void* src) {
    asm volatile("cp.async.cg.shared.global [%0], [%1], 16;\n" :: "r"(dst), "l"(src));
}
__device__ __forceinline__ void ldm_x4(uint32_t& r0, uint32_t& r1, uint32_t& r2,
                                       uint32_t& r3, uint32_t addr) {
    asm volatile("ldmatrix.sync.aligned.m8n8.x4.shared.b16 {%0,%1,%2,%3}, [%4];\n"
        : "=r"(r0), "=r"(r1), "=r"(r2), "=r"(r3) : "r"(addr));
}
__device__ __forceinline__ void ldm_x4_t(uint32_t& r0, uint32_t& r1, uint32_t& r2,
                                         uint32_t& r3, uint32_t addr) {
    asm volatile("ldmatrix.sync.aligned.m8n8.x4.trans.shared.b16 {%0,%1,%2,%3}, [%4];\n"
        : "=r"(r0), "=r"(r1), "=r"(r2), "=r"(r3) : "r"(addr));
}
__device__ __forceinline__ void ldm_x2_t(uint32_t& r0, uint32_t& r1, uint32_t addr) {
    asm volatile("ldmatrix.sync.aligned.m8n8.x2.trans.shared.b16 {%0,%1}, [%2];\n"
        : "=r"(r0), "=r"(r1) : "r"(addr));
}
__device__ __forceinline__ void mma_f16(float* d, const uint32_t* a, const uint32_t* b) {
    asm volatile("mma.sync.aligned.m16n8k16.row.col.f32.f16.f16.f32 "
        "{%0,%1,%2,%3}, {%4,%5,%6,%7}, {%8,%9}, {%0,%1,%2,%3};\n"
        : "+f"(d[0]), "+f"(d[1]), "+f"(d[2]), "+f"(d[3])
        : "r"(a[0]), "r"(a[1]), "r"(a[2]), "r"(a[3]), "r"(b[0]), "r"(b[1]));
}
__device__ __forceinline__ uint32_t ex2_f16x2(float a, float b) {
    __half2 h = __floats2half2_rn(a, b);
    uint32_t u = *reinterpret_cast<uint32_t*>(&h);
    uint32_t r;
    asm volatile("ex2.approx.f16x2 %0, %1;\n" : "=r"(r) : "r"(u));
    return r;
}

// ---------------------------------------------------------------------------
// Vectorized conversion: fp32 -> f16, 8 elems/thread
// ---------------------------------------------------------------------------
__global__ void convB_kernel(const float* __restrict__ src, __half* __restrict__ dst,
                             int total8) {
    int e = blockIdx.x * 256 + threadIdx.x;
    if (e >= total8) return;
    const float4* s = (const float4*)src + 2 * (size_t)e;
    float4 a = s[0], b = s[1];
    __half2 h0 = __floats2half2_rn(a.x, a.y);
    __half2 h1 = __floats2half2_rn(a.z, a.w);
    __half2 h2 = __floats2half2_rn(b.x, b.y);
    __half2 h3 = __floats2half2_rn(b.z, b.w);
    uint4 pk = make_uint4(*(uint32_t*)&h0, *(uint32_t*)&h1,
                          *(uint32_t*)&h2, *(uint32_t*)&h3);
    ((uint4*)dst)[e] = pk;
}

// ---------------------------------------------------------------------------
// LayerNorm (writes f16)
// ---------------------------------------------------------------------------
__global__ void __launch_bounds__(256) ln_kernel(
    const float* __restrict__ x, const float* __restrict__ g,
    const float* __restrict__ b, __half* __restrict__ out)
{
    int row = blockIdx.x;
    int tid = threadIdx.x;
    float4 v = ((const float4*)(x + (size_t)row * C_DIM))[tid];
    float s  = v.x + v.y + v.z + v.w;
    float s2 = v.x*v.x + v.y*v.y + v.z*v.z + v.w*v.w;
    __shared__ float red[64];
    #pragma unroll
    for (int o = 16; o; o >>= 1) {
        s  += __shfl_xor_sync(0xffffffffu, s,  o);
        s2 += __shfl_xor_sync(0xffffffffu, s2, o);
    }
    int warp = tid >> 5;
    if ((tid & 31) == 0) { red[warp] = s; red[32 + warp] = s2; }
    __syncthreads();
    if (tid < 32) {
        s  = (tid < 8) ? red[tid]      : 0.f;
        s2 = (tid < 8) ? red[32 + tid] : 0.f;
        #pragma unroll
        for (int o = 4; o; o >>= 1) {
            s  += __shfl_xor_sync(0xffffffffu, s,  o);
            s2 += __shfl_xor_sync(0xffffffffu, s2, o);
        }
        if (tid == 0) { red[0] = s; red[32] = s2; }
    }
    __syncthreads();
    float mean = red[0]  * (1.0f / C_DIM);
    float var  = red[32] * (1.0f / C_DIM) - mean * mean;
    float inv  = rsqrtf(var + 1e-5f);
    float4 gv = ((const float4*)g)[tid];
    float4 bv = ((const float4*)b)[tid];
    __half2 o0 = __floats2half2_rn((v.x - mean) * inv * gv.x + bv.x,
                                   (v.y - mean) * inv * gv.y + bv.y);
    __half2 o1 = __floats2half2_rn((v.z - mean) * inv * gv.z + bv.z,
                                   (v.w - mean) * inv * gv.w + bv.w);
    uint2 pk = make_uint2(*(uint32_t*)&o0, *(uint32_t*)&o1);
    *(uint2*)(out + (size_t)row * C_DIM + 4 * tid) = pk;
}

// ---------------------------------------------------------------------------
// f16 tensor-core GEMM: 5-stage cp.async pipeline (94.7 KB smem, 2 CTAs/SM),
// BM=BN=128, BK=32, 128 threads (4 warps 2x2), warp tile 64x64, single sync.
// EPI: 1 = +bias+res (fp32 out)
//      3 = +bias, exact GELU, f16 out
//      4 = +bias, fused QKV attention-operand output
//      5 = +bias, q-only attention output (x0.125 -> f16)
//      6 = +bias, kv attention output (k | v)
// ---------------------------------------------------------------------------
#define BM 128
#define BN 128
#define BK 32
#define A_PAD 40
#define B_PAD 136
#define NSTAGE 5
#define BG_SMEM (NSTAGE * (BM * A_PAD + BK * B_PAD) * 2)   // 94720 B

template<int EPI>
__global__ void __launch_bounds__(128, 2) bgemm_kernel(
    const __half* __restrict__ A, const __half* __restrict__ Bm,
    const float* __restrict__ bias, const float* __restrict__ res,
    float* __restrict__ Cf, __half* __restrict__ Ct,
    __half* __restrict__ pq, __half* __restrict__ pkh,
    __half* __restrict__ pv,
    int M, int N, int Kp)
{
    extern __shared__ char sm_raw[];
    __half* As = (__half*)sm_raw;
    __half* Bs = (__half*)(sm_raw + NSTAGE * BM * A_PAD * sizeof(__half));

    const int tid  = threadIdx.x;
    const int lane = tid & 31, wid = tid >> 5;
    const int bm0 = blockIdx.y * BM, bn0 = blockIdx.x * BN;
    const int wm = (wid & 1) * 64, wn = (wid >> 1) * 64;

    float acc[4][8][4];
    #pragma unroll
    for (int i = 0; i < 4; i++)
        #pragma unroll
        for (int j = 0; j < 8; j++)
            #pragma unroll
            for (int r = 0; r < 4; r++) acc[i][j][r] = 0.f;

    auto As_u32 = [&](int s, int r, int c) -> uint32_t {
        return (uint32_t)__cvta_generic_to_shared(As + ((s * BM + r) * A_PAD + c));
    };
    auto Bs_u32 = [&](int s, int r, int c) -> uint32_t {
        return (uint32_t)__cvta_generic_to_shared(Bs + ((s * BK + r) * B_PAD + c));
    };

    auto load_stage = [&](int s, int k0) {
        #pragma unroll
        for (int i = 0; i < 4; i++) {
            int chunk = tid + i * 128;
            int ar = chunk >> 2, ac = (chunk & 3) * 8;
            cp16(As_u32(s, ar, ac), A + (size_t)(bm0 + ar) * Kp + k0 + ac);
            int br = chunk >> 4, bc = (chunk & 15) * 8;
            cp16(Bs_u32(s, br, bc), Bm + (size_t)(k0 + br) * N + bn0 + bc);
        }
        asm volatile("cp.async.commit_group;\n" ::);
    };

    const int NK = Kp / BK;
    load_stage(0, 0);
    load_stage(1, BK);
    load_stage(2, 2 * BK);
    load_stage(3, 3 * BK);

    int s = 0, sl = 4;   // current compute stage; next stage to fill
    for (int t = 0; t < NK; t++) {
        const int rem = NK - 1 - t;
        if (rem >= 3)      asm volatile("cp.async.wait_group 3;\n" ::);
        else if (rem == 2) asm volatile("cp.async.wait_group 2;\n" ::);
        else if (rem == 1) asm volatile("cp.async.wait_group 1;\n" ::);
        else               asm volatile("cp.async.wait_group 0;\n" ::);
        __syncthreads();
        if (t + 4 < NK) {
            load_stage(sl, (t + 4) * BK);
            if (++sl == NSTAGE) sl = 0;
        }

        #pragma unroll
        for (int k16 = 0; k16 < 2; k16++) {
            uint32_t af[4][4];
            #pragma unroll
            for (int mi = 0; mi < 4; mi++) {
                uint32_t addr = As_u32(s, wm + mi * 16 + (lane & 15),
                                       k16 * 16 + ((lane >> 4) << 3));
                ldm_x4(af[mi][0], af[mi][1], af[mi][2], af[mi][3], addr);
            }
            uint32_t bfr[8][2];
            #pragma unroll
            for (int njp = 0; njp < 4; njp++) {
                int kr = k16 * 16 + ((lane >> 3) & 1) * 8 + (lane & 7);
                int nc = wn + njp * 16 + ((lane >> 4) & 1) * 8;
                uint32_t r0, r1, r2, r3;
                ldm_x4_t(r0, r1, r2, r3, Bs_u32(s, kr, nc));
                bfr[2*njp][0] = r0; bfr[2*njp][1] = r1;
                bfr[2*njp+1][0] = r2; bfr[2*njp+1][1] = r3;
            }
            #pragma unroll
            for (int mi = 0; mi < 4; mi++)
                #pragma unroll
                for (int nj = 0; nj < 8; nj++)
                    mma_f16(acc[mi][nj], af[mi], bfr[nj]);
        }
        if (++s == NSTAGE) s = 0;
    }

    const int g = lane >> 2, tig = lane & 3;
    #pragma unroll
    for (int mi = 0; mi < 4; mi++) {
        #pragma unroll
        for (int r2 = 0; r2 < 2; r2++) {
            int row = bm0 + wm + mi * 16 + g + r2 * 8;
            #pragma unroll
            for (int nj = 0; nj < 8; nj++) {
                int col = bn0 + wn + nj * 8 + tig * 2;
                float v0 = acc[mi][nj][r2 * 2 + 0] + bias[col];
                float v1 = acc[mi][nj][r2 * 2 + 1] + bias[col + 1];
                if (EPI == 1) {
                    float2 rv = *(const float2*)(res + (size_t)row * N + col);
                    v0 += rv.x; v1 += rv.y;
                    *(float2*)(Cf + (size_t)row * N + col) = make_float2(v0, v1);
                }
                if (EPI == 3) {
                    v0 = 0.5f * v0 * (1.0f + erff(v0 * 0.7071067811865475f));
                    v1 = 0.5f * v1 * (1.0f + erff(v1 * 0.7071067811865475f));
                    *(__half2*)(Ct + (size_t)row * N + col) = __floats2half2_rn(v0, v1);
                }
                if (EPI >= 4) {
                    int kind = (EPI == 5) ? 0
                             : (EPI == 4) ? (col >> 10)
                             : ((col >> 10) + 1);
                    int cc = (EPI == 5) ? col : (col & 1023);
                    int hh = cc >> 6, dd = cc & 63;
                    int b_ = row >> 10, t_ = row & 1023;
                    size_t oidx = ((size_t)((b_ * 16 + hh) * 1024) + t_) * 64 + dd;
                    if (kind == 0) {
                        *(__half2*)(pq + oidx) =
                            __floats2half2_rn(v0 * 0.125f, v1 * 0.125f);
                    } else if (kind == 1) {
                        *(__half2*)(pkh + oidx) = __floats2half2_rn(v0, v1);
                    } else {
                        *(__half2*)(pv + oidx) = __floats2half2_rn(v0, v1);
                    }
                }
            }
        }
    }
}

// ---------------------------------------------------------------------------
// Tensor-core flash attention v3 (R10/R11-proven)
// ---------------------------------------------------------------------------
#define FD 72
#define FTILE (64 * FD)
#define FMHA_SMEM (5 * FTILE * 2)

template<bool CAUSAL>
__global__ void __launch_bounds__(128) fmha_kernel(
    const __half* __restrict__ Qh_, const __half* __restrict__ Kh_,
    const __half* __restrict__ Vh_, __half* __restrict__ Op)
{
    const int qt = CAUSAL ? (gridDim.x - 1 - (int)blockIdx.x) : blockIdx.x;
    const int h = blockIdx.y, b = blockIdx.z;
    const int bh = b * H_HEADS + h;
    const int tid = threadIdx.x;
    const int lane = tid & 31, wid = tid >> 5;

    extern __shared__ __half sm[];
    __half* sQ = sm;
    auto sK = [&](int s) { return sm + FTILE + (s * 2) * FTILE; };
    auto sV = [&](int s) { return sm + FTILE + (s * 2 + 1) * FTILE; };

    const size_t qbase  = ((size_t)bh * T_SEQ + qt * 64) * 64;
    const size_t kvbase = (size_t)bh * T_SEQ * 64;

    const int ntiles = CAUSAL ? (qt + 1) : (T_SEQ / 64);

    for (int idx = tid; idx < 64 * 8; idx += 128) {
        int pos = idx >> 3, c = 64 + (idx & 7);
        sV(0)[pos * FD + c] = (c == 64) ? __float2half(1.0f) : __float2half(0.0f);
        sV(1)[pos * FD + c] = (c == 64) ? __float2half(1.0f) : __float2half(0.0f);
    }

    auto load_q = [&]() {
        #pragma unroll
        for (int i = 0; i < 4; i++) {
            int chunk = tid + i * 128;
            int r = chunk >> 3, c8 = (chunk & 7) * 8;
            cp16((uint32_t)__cvta_generic_to_shared(sQ + r * FD + c8), Qh_ + qbase + r * 64 + c8);
        }
    };
    auto load_kv = [&](int s, int kt) {
        #pragma unroll
        for (int i = 0; i < 4; i++) {
            int chunk = tid + i * 128;
            int r = chunk >> 3, c8 = (chunk & 7) * 8;
            size_t src = kvbase + (size_t)(kt * 64 + r) * 64 + c8;
            cp16((uint32_t)__cvta_generic_to_shared(sK(s) + r * FD + c8), Kh_ + src);
            cp16((uint32_t)__cvta_generic_to_shared(sV(s) + r * FD + c8), Vh_ + src);
        }
    };

    load_q();
    load_kv(0, 0);
    asm volatile("cp.async.commit_group;\n" ::);
    if (ntiles > 1) load_kv(1, 1);
    asm volatile("cp.async.commit_group;\n" ::);

    float oa[9][4];
    #pragma unroll
    for (int n = 0; n < 9; n++)
        #pragma unroll
        for (int r = 0; r < 4; r++) oa[n][r] = 0.f;
    float m0 = -1e30f, m1 = -1e30f;

    const int g = lane >> 2, tq = lane & 3;

    for (int kt = 0; kt < ntiles; kt++) {
        const int s = kt & 1;
        if (kt + 1 < ntiles) asm volatile("cp.async.wait_group 1;\n" ::);
        else                 asm volatile("cp.async.wait_group 0;\n" ::);
        __syncthreads();

        float sa[8][4];
        #pragma unroll
        for (int n = 0; n < 8; n++)
            #pragma unroll
            for (int r = 0; r < 4; r++) sa[n][r] = 0.f;

        {
            const __half* Kp = sK(s);
            #pragma unroll
            for (int kc = 0; kc < 4; kc++) {
                uint32_t a[4];
                ldm_x4(a[0], a[1], a[2], a[3],
                    (uint32_t)__cvta_generic_to_shared(
                        sQ + (wid * 16 + (lane & 15)) * FD + kc * 16 + ((lane >> 4) << 3)));
                #pragma unroll
                for (int njp = 0; njp < 4; njp++) {
                    uint32_t r0, r1, r2, r3;
                    ldm_x4(r0, r1, r2, r3,
                        (uint32_t)__cvta_generic_to_shared(
                            Kp + (njp * 16 + ((lane >> 4) & 1) * 8 + (lane & 7)) * FD
                               + kc * 16 + ((lane >> 3) & 1) * 8));
                    uint32_t b0[2] = { r0, r1 }, b1[2] = { r2, r3 };
                    mma_f16(sa[2*njp],   a, b0);
                    mma_f16(sa[2*njp+1], a, b1);
                }
            }
        }

        if (CAUSAL && kt == qt) {
            int q0l = wid * 16 + g;
            #pragma unroll
            for (int nj = 0; nj < 8; nj++) {
                int c0 = nj * 8 + 2 * tq;
                if (c0     > q0l)     sa[nj][0] = -1e30f;
                if (c0 + 1 > q0l)     sa[nj][1] = -1e30f;
                if (c0     > q0l + 8) sa[nj][2] = -1e30f;
                if (c0 + 1 > q0l + 8) sa[nj][3] = -1e30f;
            }
        }

        float mx0 = -1e30f, mx1 = -1e30f;
        #pragma unroll
        for (int nj = 0; nj < 8; nj++) {
            mx0 = fmaxf(mx0, fmaxf(sa[nj][0], sa[nj][1]));
            mx1 = fmaxf(mx1, fmaxf(sa[nj][2], sa[nj][3]));
        }
        #pragma unroll
        for (int o = 1; o <= 2; o <<= 1) {
            mx0 = fmaxf(mx0, __shfl_xor_sync(0xffffffffu, mx0, o));
            mx1 = fmaxf(mx1, __shfl_xor_sync(0xffffffffu, mx1, o));
        }
        float mn0 = fmaxf(m0, mx0), mn1 = fmaxf(m1, mx1);
        float tm0 = mn0 * L2E, tm1 = mn1 * L2E;
        float corr0 = exp2f(m0 * L2E - tm0);
        float corr1 = exp2f(m1 * L2E - tm1);
        m0 = mn0; m1 = mn1;
        #pragma unroll
        for (int n = 0; n < 9; n++) {
            oa[n][0] *= corr0; oa[n][1] *= corr0;
            oa[n][2] *= corr1; oa[n][3] *= corr1;
        }
        uint32_t pf[8][2];
        #pragma unroll
        for (int nj = 0; nj < 8; nj++) {
            pf[nj][0] = ex2_f16x2(fmaf(sa[nj][0], L2E, -tm0), fmaf(sa[nj][1], L2E, -tm0));
            pf[nj][1] = ex2_f16x2(fmaf(sa[nj][2], L2E, -tm1), fmaf(sa[nj][3], L2E, -tm1));
        }

        {
            const __half* Vt = sV(s);
            #pragma unroll
            for (int kc = 0; kc < 4; kc++) {
                uint32_t a[4] = { pf[2*kc][0], pf[2*kc][1], pf[2*kc+1][0], pf[2*kc+1][1] };
                #pragma unroll
                for (int njp = 0; njp < 4; njp++) {
                    uint32_t r0, r1, r2, r3;
                    ldm_x4_t(r0, r1, r2, r3,
                        (uint32_t)__cvta_generic_to_shared(
                            Vt + (kc * 16 + ((lane >> 3) & 1) * 8 + (lane & 7)) * FD
                               + njp * 16 + ((lane >> 4) & 1) * 8));
                    uint32_t b0[2] = { r0, r1 }, b1[2] = { r2, r3 };
                    mma_f16(oa[2*njp],   a, b0);
                    mma_f16(oa[2*njp+1], a, b1);
                }
                uint32_t r0, r1;
                ldm_x2_t(r0, r1,
                    (uint32_t)__cvta_generic_to_shared(
                        Vt + (kc * 16 + (lane & 15)) * FD + 64));
                uint32_t b2[2] = { r0, r1 };
                mma_f16(oa[8], a, b2);
            }
        }

        __syncthreads();
        if (kt + 2 < ntiles) load_kv(s, kt + 2);
        asm volatile("cp.async.commit_group;\n" ::);
    }

    float l0 = __shfl_sync(0xffffffffu, oa[8][0], lane & ~3);
    float l1 = __shfl_sync(0xffffffffu, oa[8][2], lane & ~3);
    float inv0 = 1.0f / l0, inv1 = 1.0f / l1;

    size_t r0 = (size_t)b * T_SEQ + qt * 64 + wid * 16 + g;
    size_t r1 = r0 + 8;
    #pragma unroll
    for (int nj = 0; nj < 8; nj++) {
        int col = h * 64 + nj * 8 + 2 * tq;
        *(__half2*)(Op + r0 * C_DIM + col) =
            __floats2half2_rn(oa[nj][0] * inv0, oa[nj][1] * inv0);
        *(__half2*)(Op + r1 * C_DIM + col) =
            __floats2half2_rn(oa[nj][2] * inv1, oa[nj][3] * inv1);
    }
}

// ---------------------------------------------------------------------------
// Launch: R12-proven fork-join schedule (kv GEMM waits for fmha_self).
// Only diff vs R12: GEMM kernels use NSTAGE=5.
// ---------------------------------------------------------------------------
static inline int cdiv(int a, int b) { return (a + b - 1) / b; }

extern "C" void kernel_launch(void* const* d_in, const int* in_sizes, int n_in,
                              void* d_out, int out_size)
{
    const float* x           = (const float*)d_in[0];
    const float* context     = (const float*)d_in[1];
    const float* ln1_g       = (const float*)d_in[2];
    const float* ln1_b       = (const float*)d_in[3];
    const float* qkv_w       = (const float*)d_in[4];
    const float* qkv_b       = (const float*)d_in[5];
    const float* attn_out_w  = (const float*)d_in[6];
    const float* attn_out_b  = (const float*)d_in[7];
    const float* lnc_g       = (const float*)d_in[8];
    const float* lnc_b       = (const float*)d_in[9];
    const float* q_w         = (const float*)d_in[10];
    const float* q_b         = (const float*)d_in[11];
    const float* kv_w        = (const float*)d_in[12];
    const float* kv_b        = (const float*)d_in[13];
    const float* cross_out_w = (const float*)d_in[14];
    const float* cross_out_b = (const float*)d_in[15];
    const float* ln2_g       = (const float*)d_in[16];
    const float* ln2_b       = (const float*)d_in[17];
    const float* ffn_w1      = (const float*)d_in[18];
    const float* ffn_b1      = (const float*)d_in[19];
    const float* ffn_w2      = (const float*)d_in[20];
    const float* ffn_b2      = (const float*)d_in[21];
    float* out = (float*)d_out;

    float *x1, *x2;
    __half *h2, *attn2, *ctx2, *ffn2a;
    __half *wqkv2, *wao2, *wq2, *wkv2, *wco2, *wf1, *wf2;
    __half *qh, *kh, *vh;
    cudaGetSymbolAddress((void**)&x1,    g_x1);
    cudaGetSymbolAddress((void**)&x2,    g_x2);
    cudaGetSymbolAddress((void**)&h2,    g_h2);
    cudaGetSymbolAddress((void**)&attn2, g_attn2);
    cudaGetSymbolAddress((void**)&ctx2,  g_ctx2);
    cudaGetSymbolAddress((void**)&ffn2a, g_ffn2a);
    cudaGetSymbolAddress((void**)&wqkv2, w_qkv2);
    cudaGetSymbolAddress((void**)&wao2,  w_ao2);
    cudaGetSymbolAddress((void**)&wq2,   w_q2);
    cudaGetSymbolAddress((void**)&wkv2,  w_kv2);
    cudaGetSymbolAddress((void**)&wco2,  w_co2);
    cudaGetSymbolAddress((void**)&wf1,   w_f1_2);
    cudaGetSymbolAddress((void**)&wf2,   w_f2_2);
    cudaGetSymbolAddress((void**)&qh, a_qh);
    cudaGetSymbolAddress((void**)&kh, a_kh);
    cudaGetSymbolAddress((void**)&vh, a_vh);

    cudaFuncSetAttribute(bgemm_kernel<1>, cudaFuncAttributeMaxDynamicSharedMemorySize, BG_SMEM);
    cudaFuncSetAttribute(bgemm_kernel<3>, cudaFuncAttributeMaxDynamicSharedMemorySize, BG_SMEM);
    cudaFuncSetAttribute(bgemm_kernel<4>, cudaFuncAttributeMaxDynamicSharedMemorySize, BG_SMEM);
    cudaFuncSetAttribute(bgemm_kernel<5>, cudaFuncAttributeMaxDynamicSharedMemorySize, BG_SMEM);
    cudaFuncSetAttribute(bgemm_kernel<6>, cudaFuncAttributeMaxDynamicSharedMemorySize, BG_SMEM);
    cudaFuncSetAttribute(fmha_kernel<true>,  cudaFuncAttributeMaxDynamicSharedMemorySize, FMHA_SMEM);
    cudaFuncSetAttribute(fmha_kernel<false>, cudaFuncAttributeMaxDynamicSharedMemorySize, FMHA_SMEM);

    const int M = M_ROWS, C = C_DIM, F = F_DIM;
    dim3 fgrid(T_SEQ / 64, H_HEADS, 4);

    // --- fork-join infrastructure (leaked; kernel_launch runs only ~3x) ---
    cudaStream_t sB;
    cudaStreamCreateWithFlags(&sB, cudaStreamNonBlocking);
    cudaEvent_t evFork, evWqkv, evConvs, evSelf, evKV;
    cudaEventCreateWithFlags(&evFork,  cudaEventDisableTiming);
    cudaEventCreateWithFlags(&evWqkv,  cudaEventDisableTiming);
    cudaEventCreateWithFlags(&evConvs, cudaEventDisableTiming);
    cudaEventCreateWithFlags(&evSelf,  cudaEventDisableTiming);
    cudaEventCreateWithFlags(&evKV,    cudaEventDisableTiming);

    // fork
    cudaEventRecord(evFork, 0);
    cudaStreamWaitEvent(sB, evFork, 0);

    // Stream B: conversions (wqkv first so the qkv GEMM can start ASAP)
    convB_kernel<<<cdiv(C * 3 * C / 8, 256), 256, 0, sB>>>(qkv_w, wqkv2, C * 3 * C / 8);
    cudaEventRecord(evWqkv, sB);
    convB_kernel<<<cdiv(C * C / 8,     256), 256, 0, sB>>>(attn_out_w,  wao2, C * C / 8);
    convB_kernel<<<cdiv(C * C / 8,     256), 256, 0, sB>>>(q_w,         wq2,  C * C / 8);
    convB_kernel<<<cdiv(C * 2 * C / 8, 256), 256, 0, sB>>>(kv_w,        wkv2, C * 2 * C / 8);
    convB_kernel<<<cdiv(M * C / 8,     256), 256, 0, sB>>>(context,     ctx2, M * C / 8);
    convB_kernel<<<cdiv(C * C / 8,     256), 256, 0, sB>>>(cross_out_w, wco2, C * C / 8);
    convB_kernel<<<cdiv(C * F / 8,     256), 256, 0, sB>>>(ffn_w1,      wf1,  C * F / 8);
    convB_kernel<<<cdiv(F * C / 8,     256), 256, 0, sB>>>(ffn_w2,      wf2,  F * C / 8);
    cudaEventRecord(evConvs, sB);

    // Stream A (default): LN1, qkv GEMM (after wqkv2), self-attention
    ln_kernel<<<M, 256>>>(x, ln1_g, ln1_b, h2);
    cudaStreamWaitEvent(0, evWqkv, 0);
    bgemm_kernel<4><<<dim3(3 * C / BN, M / BM), 128, BG_SMEM>>>(
        h2, wqkv2, qkv_b, nullptr, nullptr, nullptr,
        qh, kh, vh, M, 3 * C, C);
    fmha_kernel<true><<<fgrid, 128, FMHA_SMEM>>>(qh, kh, vh, attn2);
    cudaEventRecord(evSelf, 0);

    // Stream B: kv GEMM (waits for fmha_self — it overwrites kh/vh)
    cudaStreamWaitEvent(sB, evSelf, 0);
    bgemm_kernel<6><<<dim3(2 * C / BN, M / BM), 128, BG_SMEM, sB>>>(
        ctx2, wkv2, kv_b, nullptr, nullptr, nullptr,
        nullptr, kh, vh, M, 2 * C, C);
    cudaEventRecord(evKV, sB);

    // Stream A: attn_out (needs wao2 -> evConvs), LNc, q GEMM
    cudaStreamWaitEvent(0, evConvs, 0);
    bgemm_kernel<1><<<dim3(C / BN, M / BM), 128, BG_SMEM>>>(
        attn2, wao2, attn_out_b, x, x1, nullptr,
        nullptr, nullptr, nullptr, M, C, C);
    ln_kernel<<<M, 256>>>(x1, lnc_g, lnc_b, h2);
    bgemm_kernel<5><<<dim3(C / BN, M / BM), 128, BG_SMEM>>>(
        h2, wq2, q_b, nullptr, nullptr, nullptr,
        qh, nullptr, nullptr, M, C, C);

    // join: cross-attention needs kv GEMM output
    cudaStreamWaitEvent(0, evKV, 0);
    fmha_kernel<false><<<fgrid, 128, FMHA_SMEM>>>(qh, kh, vh, attn2);
    bgemm_kernel<1><<<dim3(C / BN, M / BM), 128, BG_SMEM>>>(
        attn2, wco2, cross_out_b, x1, x2, nullptr,
        nullptr, nullptr, nullptr, M, C, C);

    // FFN
    ln_kernel<<<M, 256>>>(x2, ln2_g, ln2_b, h2);
    bgemm_kernel<3><<<dim3(F / BN, M / BM), 128, BG_SMEM>>>(
        h2, wf1, ffn_b1, nullptr, nullptr, ffn2a,
        nullptr, nullptr, nullptr, M, F, C);
    bgemm_kernel<1><<<dim3(C / BN, M / BM), 128, BG_SMEM>>>(
        ffn2a, wf2, ffn_b2, x2, out, nullptr,
        nullptr, nullptr, nullptr, M, C, F);
}

// round 16
// speedup vs baseline: 1.0207x; 1.0150x over previous
#include <cuda_runtime.h>
#include <cuda_bf16.h>
#include <cuda_fp16.h>
#include <cstdint>
#include <math.h>

// ---------------------------------------------------------------------------
// Problem constants: B=4, T=1024, C=1024, H=16, D=64, F=4096, M=B*T=4096
// ---------------------------------------------------------------------------
#define M_ROWS 4096
#define C_DIM  1024
#define T_SEQ  1024
#define H_HEADS 16
#define F_DIM  4096
#define L2E 1.4426950408889634f

// ---------------------------------------------------------------------------
// Scratch (device globals)
// ---------------------------------------------------------------------------
__device__ float g_x1 [M_ROWS * C_DIM];
__device__ float g_x2 [M_ROWS * C_DIM];

__device__ __half g_h2   [M_ROWS * C_DIM];
__device__ __half g_attn2[M_ROWS * C_DIM];
__device__ __half g_ctx2 [M_ROWS * C_DIM];
__device__ __half g_ffn2a[(size_t)M_ROWS * F_DIM];

__device__ __half w_qkv2[C_DIM * 3 * C_DIM];
__device__ __half w_ao2 [C_DIM * C_DIM];
__device__ __half w_q2  [C_DIM * C_DIM];
__device__ __half w_kv2 [C_DIM * 2 * C_DIM];
__device__ __half w_co2 [C_DIM * C_DIM];
__device__ __half w_f1_2[C_DIM * F_DIM];
__device__ __half w_f2_2[(size_t)F_DIM * C_DIM];

#define ATT_ELEMS (4 * H_HEADS * T_SEQ * 64)
__device__ __half a_qh[ATT_ELEMS];
__device__ __half a_kh[ATT_ELEMS];
__device__ __half a_vh[ATT_ELEMS];

// ---------------------------------------------------------------------------
// Helpers
// ---------------------------------------------------------------------------
__device__ __forceinline__ void cp16(uint32_t dst, const void* src) {
    asm volatile("cp.async.cg.shared.global [%0], [%1], 16;\n" :: "r"(dst), "l"(src));
}
__device__ __forceinline__ void ldm_x4(uint32_t& r0, uint32_t& r1, uint32_t& r2,
                                       uint32_t& r3, uint32_t addr) {
    asm volatile("ldmatrix.sync.aligned.m8n8.x4.shared.b16 {%0,%1,%2,%3}, [%4];\n"
        : "=r"(r0), "=r"(r1), "=r"(r2), "=r"(r3) : "r"(addr));
}
__device__ __forceinline__ void ldm_x4_t(uint32_t& r0, uint32_t& r1, uint32_t& r2,
                                         uint32_t& r3, uint32_t addr) {
    asm volatile("ldmatrix.sync.aligned.m8n8.x4.trans.shared.b16 {%0,%1,%2,%3}, [%4];\n"
        : "=r"(r0), "=r"(r1), "=r"(r2), "=r"(r3) : "r"(addr));
}
__device__ __forceinline__ void ldm_x2_t(uint32_t& r0, uint32_t& r1, uint32_t addr) {
    asm volatile("ldmatrix.sync.aligned.m8n8.x2.trans.shared.b16 {%0,%1}, [%2];\n"
        : "=r"(r0), "=r"(r1) : "r"(addr));
}
__device__ __forceinline__ void mma_f16(float* d, const uint32_t* a, const uint32_t* b) {
    asm volatile("mma.sync.aligned.m16n8k16.row.col.f32.f16.f16.f32 "
        "{%0,%1,%2,%3}, {%4,%5,%6,%7}, {%8,%9}, {%0,%1,%2,%3};\n"
        : "+f"(d[0]), "+f"(d[1]), "+f"(d[2]), "+f"(d[3])
        : "r"(a[0]), "r"(a[1]), "r"(a[2]), "r"(a[3]), "r"(b[0]), "r"(b[1]));
}
__device__ __forceinline__ uint32_t ex2_f16x2(float a, float b) {
    __half2 h = __floats2half2_rn(a, b);
    uint32_t u = *reinterpret_cast<uint32_t*>(&h);
    uint32_t r;
    asm volatile("ex2.approx.f16x2 %0, %1;\n" : "=r"(r) : "r"(u));
    return r;
}

// ---------------------------------------------------------------------------
// Vectorized conversion: fp32 -> f16, 8 elems/thread
// ---------------------------------------------------------------------------
__global__ void convB_kernel(const float* __restrict__ src, __half* __restrict__ dst,
                             int total8) {
    int e = blockIdx.x * 256 + threadIdx.x;
    if (e >= total8) return;
    const float4* s = (const float4*)src + 2 * (size_t)e;
    float4 a = s[0], b = s[1];
    __half2 h0 = __floats2half2_rn(a.x, a.y);
    __half2 h1 = __floats2half2_rn(a.z, a.w);
    __half2 h2 = __floats2half2_rn(b.x, b.y);
    __half2 h3 = __floats2half2_rn(b.z, b.w);
    uint4 pk = make_uint4(*(uint32_t*)&h0, *(uint32_t*)&h1,
                          *(uint32_t*)&h2, *(uint32_t*)&h3);
    ((uint4*)dst)[e] = pk;
}

// ---------------------------------------------------------------------------
// LayerNorm (writes f16)
// ---------------------------------------------------------------------------
__global__ void __launch_bounds__(256) ln_kernel(
    const float* __restrict__ x, const float* __restrict__ g,
    const float* __restrict__ b, __half* __restrict__ out)
{
    int row = blockIdx.x;
    int tid = threadIdx.x;
    float4 v = ((const float4*)(x + (size_t)row * C_DIM))[tid];
    float s  = v.x + v.y + v.z + v.w;
    float s2 = v.x*v.x + v.y*v.y + v.z*v.z + v.w*v.w;
    __shared__ float red[64];
    #pragma unroll
    for (int o = 16; o; o >>= 1) {
        s  += __shfl_xor_sync(0xffffffffu, s,  o);
        s2 += __shfl_xor_sync(0xffffffffu, s2, o);
    }
    int warp = tid >> 5;
    if ((tid & 31) == 0) { red[warp] = s; red[32 + warp] = s2; }
    __syncthreads();
    if (tid < 32) {
        s  = (tid < 8) ? red[tid]      : 0.f;
        s2 = (tid < 8) ? red[32 + tid] : 0.f;
        #pragma unroll
        for (int o = 4; o; o >>= 1) {
            s  += __shfl_xor_sync(0xffffffffu, s,  o);
            s2 += __shfl_xor_sync(0xffffffffu, s2, o);
        }
        if (tid == 0) { red[0] = s; red[32] = s2; }
    }
    __syncthreads();
    float mean = red[0]  * (1.0f / C_DIM);
    float var  = red[32] * (1.0f / C_DIM) - mean * mean;
    float inv  = rsqrtf(var + 1e-5f);
    float4 gv = ((const float4*)g)[tid];
    float4 bv = ((const float4*)b)[tid];
    __half2 o0 = __floats2half2_rn((v.x - mean) * inv * gv.x + bv.x,
                                   (v.y - mean) * inv * gv.y + bv.y);
    __half2 o1 = __floats2half2_rn((v.z - mean) * inv * gv.z + bv.z,
                                   (v.w - mean) * inv * gv.w + bv.w);
    uint2 pk = make_uint2(*(uint32_t*)&o0, *(uint32_t*)&o1);
    *(uint2*)(out + (size_t)row * C_DIM + 4 * tid) = pk;
}

// ---------------------------------------------------------------------------
// f16 tensor-core GEMM (exact R12-proven: 4-stage, single sync, 2 CTAs/SM)
// EPI: 1 = +bias+res (fp32 out)
//      3 = +bias, exact GELU, f16 out
//      4 = +bias, fused QKV attention-operand output
//      5 = +bias, q-only attention output (x0.125 -> f16)
//      6 = +bias, kv attention output (k | v)
// ---------------------------------------------------------------------------
#define BM 128
#define BN 128
#define BK 32
#define A_PAD 40
#define B_PAD 136
#define NSTAGE 4
#define BG_SMEM (NSTAGE * (BM * A_PAD + BK * B_PAD) * 2)   // 75776 B

template<int EPI>
__global__ void __launch_bounds__(128, 2) bgemm_kernel(
    const __half* __restrict__ A, const __half* __restrict__ Bm,
    const float* __restrict__ bias, const float* __restrict__ res,
    float* __restrict__ Cf, __half* __restrict__ Ct,
    __half* __restrict__ pq, __half* __restrict__ pkh,
    __half* __restrict__ pv,
    int M, int N, int Kp)
{
    extern __shared__ char sm_raw[];
    __half* As = (__half*)sm_raw;
    __half* Bs = (__half*)(sm_raw + NSTAGE * BM * A_PAD * sizeof(__half));

    const int tid  = threadIdx.x;
    const int lane = tid & 31, wid = tid >> 5;
    const int bm0 = blockIdx.y * BM, bn0 = blockIdx.x * BN;
    const int wm = (wid & 1) * 64, wn = (wid >> 1) * 64;

    float acc[4][8][4];
    #pragma unroll
    for (int i = 0; i < 4; i++)
        #pragma unroll
        for (int j = 0; j < 8; j++)
            #pragma unroll
            for (int r = 0; r < 4; r++) acc[i][j][r] = 0.f;

    auto As_u32 = [&](int s, int r, int c) -> uint32_t {
        return (uint32_t)__cvta_generic_to_shared(As + ((s * BM + r) * A_PAD + c));
    };
    auto Bs_u32 = [&](int s, int r, int c) -> uint32_t {
        return (uint32_t)__cvta_generic_to_shared(Bs + ((s * BK + r) * B_PAD + c));
    };

    auto load_stage = [&](int s, int k0) {
        #pragma unroll
        for (int i = 0; i < 4; i++) {
            int chunk = tid + i * 128;
            int ar = chunk >> 2, ac = (chunk & 3) * 8;
            cp16(As_u32(s, ar, ac), A + (size_t)(bm0 + ar) * Kp + k0 + ac);
            int br = chunk >> 4, bc = (chunk & 15) * 8;
            cp16(Bs_u32(s, br, bc), Bm + (size_t)(k0 + br) * N + bn0 + bc);
        }
        asm volatile("cp.async.commit_group;\n" ::);
    };

    const int NK = Kp / BK;
    load_stage(0, 0);
    load_stage(1, BK);
    load_stage(2, 2 * BK);

    for (int t = 0; t < NK; t++) {
        const int rem = NK - 1 - t;
        if (rem >= 2)      asm volatile("cp.async.wait_group 2;\n" ::);
        else if (rem == 1) asm volatile("cp.async.wait_group 1;\n" ::);
        else               asm volatile("cp.async.wait_group 0;\n" ::);
        __syncthreads();
        if (t + 3 < NK) load_stage((t + 3) & 3, (t + 3) * BK);
        const int s = t & 3;

        #pragma unroll
        for (int k16 = 0; k16 < 2; k16++) {
            uint32_t af[4][4];
            #pragma unroll
            for (int mi = 0; mi < 4; mi++) {
                uint32_t addr = As_u32(s, wm + mi * 16 + (lane & 15),
                                       k16 * 16 + ((lane >> 4) << 3));
                ldm_x4(af[mi][0], af[mi][1], af[mi][2], af[mi][3], addr);
            }
            uint32_t bfr[8][2];
            #pragma unroll
            for (int njp = 0; njp < 4; njp++) {
                int kr = k16 * 16 + ((lane >> 3) & 1) * 8 + (lane & 7);
                int nc = wn + njp * 16 + ((lane >> 4) & 1) * 8;
                uint32_t r0, r1, r2, r3;
                ldm_x4_t(r0, r1, r2, r3, Bs_u32(s, kr, nc));
                bfr[2*njp][0] = r0; bfr[2*njp][1] = r1;
                bfr[2*njp+1][0] = r2; bfr[2*njp+1][1] = r3;
            }
            #pragma unroll
            for (int mi = 0; mi < 4; mi++)
                #pragma unroll
                for (int nj = 0; nj < 8; nj++)
                    mma_f16(acc[mi][nj], af[mi], bfr[nj]);
        }
    }

    const int g = lane >> 2, tig = lane & 3;
    #pragma unroll
    for (int mi = 0; mi < 4; mi++) {
        #pragma unroll
        for (int r2 = 0; r2 < 2; r2++) {
            int row = bm0 + wm + mi * 16 + g + r2 * 8;
            #pragma unroll
            for (int nj = 0; nj < 8; nj++) {
                int col = bn0 + wn + nj * 8 + tig * 2;
                float v0 = acc[mi][nj][r2 * 2 + 0] + bias[col];
                float v1 = acc[mi][nj][r2 * 2 + 1] + bias[col + 1];
                if (EPI == 1) {
                    float2 rv = *(const float2*)(res + (size_t)row * N + col);
                    v0 += rv.x; v1 += rv.y;
                    *(float2*)(Cf + (size_t)row * N + col) = make_float2(v0, v1);
                }
                if (EPI == 3) {
                    v0 = 0.5f * v0 * (1.0f + erff(v0 * 0.7071067811865475f));
                    v1 = 0.5f * v1 * (1.0f + erff(v1 * 0.7071067811865475f));
                    *(__half2*)(Ct + (size_t)row * N + col) = __floats2half2_rn(v0, v1);
                }
                if (EPI >= 4) {
                    int kind = (EPI == 5) ? 0
                             : (EPI == 4) ? (col >> 10)
                             : ((col >> 10) + 1);
                    int cc = (EPI == 5) ? col : (col & 1023);
                    int hh = cc >> 6, dd = cc & 63;
                    int b_ = row >> 10, t_ = row & 1023;
                    size_t oidx = ((size_t)((b_ * 16 + hh) * 1024) + t_) * 64 + dd;
                    if (kind == 0) {
                        *(__half2*)(pq + oidx) =
                            __floats2half2_rn(v0 * 0.125f, v1 * 0.125f);
                    } else if (kind == 1) {
                        *(__half2*)(pkh + oidx) = __floats2half2_rn(v0, v1);
                    } else {
                        *(__half2*)(pv + oidx) = __floats2half2_rn(v0, v1);
                    }
                }
            }
        }
    }
}

// ---------------------------------------------------------------------------
// Tensor-core flash attention v4: BQ=128 (256 threads, 8 warps), BKV=64.
// Same per-warp 16x64 fragment math as v3; KV tile-iterations halve.
// smem = Q(128x72) + 2 stages x (K,V) = 54 KB.
// ---------------------------------------------------------------------------
#define FD 72
#define FTILE (64 * FD)
#define FMHA_SMEM ((2 * FTILE + 4 * FTILE) * 2)   // 55296 B

template<bool CAUSAL>
__global__ void __launch_bounds__(256) fmha_kernel(
    const __half* __restrict__ Qh_, const __half* __restrict__ Kh_,
    const __half* __restrict__ Vh_, __half* __restrict__ Op)
{
    const int qt = CAUSAL ? (gridDim.x - 1 - (int)blockIdx.x) : blockIdx.x;
    const int h = blockIdx.y, b = blockIdx.z;
    const int bh = b * H_HEADS + h;
    const int tid = threadIdx.x;
    const int lane = tid & 31, wid = tid >> 5;    // wid 0..7 -> q rows wid*16

    extern __shared__ __half sm[];
    __half* sQ = sm;                               // [128][72]
    auto sK = [&](int s) { return sm + 2 * FTILE + (s * 2) * FTILE; };
    auto sV = [&](int s) { return sm + 2 * FTILE + (s * 2 + 1) * FTILE; };

    const size_t qbase  = ((size_t)bh * T_SEQ + qt * 128) * 64;
    const size_t kvbase = (size_t)bh * T_SEQ * 64;

    const int ntiles = CAUSAL ? (2 * qt + 2) : (T_SEQ / 64);

    // V padding init: col 64 = 1.0, cols 65..71 = 0 (both stages)
    for (int idx = tid; idx < 64 * 8; idx += 256) {
        int pos = idx >> 3, c = 64 + (idx & 7);
        sV(0)[pos * FD + c] = (c == 64) ? __float2half(1.0f) : __float2half(0.0f);
        sV(1)[pos * FD + c] = (c == 64) ? __float2half(1.0f) : __float2half(0.0f);
    }

    auto load_q = [&]() {
        #pragma unroll
        for (int i = 0; i < 4; i++) {
            int chunk = tid + i * 256;             // 1024 chunks: 128 rows x 8
            int r = chunk >> 3, c8 = (chunk & 7) * 8;
            cp16((uint32_t)__cvta_generic_to_shared(sQ + r * FD + c8), Qh_ + qbase + r * 64 + c8);
        }
    };
    auto load_kv = [&](int s, int kt) {
        #pragma unroll
        for (int i = 0; i < 2; i++) {
            int chunk = tid + i * 256;             // 512 chunks: 64 rows x 8
            int r = chunk >> 3, c8 = (chunk & 7) * 8;
            size_t src = kvbase + (size_t)(kt * 64 + r) * 64 + c8;
            cp16((uint32_t)__cvta_generic_to_shared(sK(s) + r * FD + c8), Kh_ + src);
            cp16((uint32_t)__cvta_generic_to_shared(sV(s) + r * FD + c8), Vh_ + src);
        }
    };

    load_q();
    load_kv(0, 0);
    asm volatile("cp.async.commit_group;\n" ::);
    if (ntiles > 1) load_kv(1, 1);
    asm volatile("cp.async.commit_group;\n" ::);

    float oa[9][4];
    #pragma unroll
    for (int n = 0; n < 9; n++)
        #pragma unroll
        for (int r = 0; r < 4; r++) oa[n][r] = 0.f;
    float m0 = -1e30f, m1 = -1e30f;

    const int g = lane >> 2, tq = lane & 3;

    for (int kt = 0; kt < ntiles; kt++) {
        const int s = kt & 1;
        if (kt + 1 < ntiles) asm volatile("cp.async.wait_group 1;\n" ::);
        else                 asm volatile("cp.async.wait_group 0;\n" ::);
        __syncthreads();

        float sa[8][4];
        #pragma unroll
        for (int n = 0; n < 8; n++)
            #pragma unroll
            for (int r = 0; r < 4; r++) sa[n][r] = 0.f;

        // S = Q * K (single pass)
        {
            const __half* Kp = sK(s);
            #pragma unroll
            for (int kc = 0; kc < 4; kc++) {
                uint32_t a[4];
                ldm_x4(a[0], a[1], a[2], a[3],
                    (uint32_t)__cvta_generic_to_shared(
                        sQ + (wid * 16 + (lane & 15)) * FD + kc * 16 + ((lane >> 4) << 3)));
                #pragma unroll
                for (int njp = 0; njp < 4; njp++) {
                    uint32_t r0, r1, r2, r3;
                    ldm_x4(r0, r1, r2, r3,
                        (uint32_t)__cvta_generic_to_shared(
                            Kp + (njp * 16 + ((lane >> 4) & 1) * 8 + (lane & 7)) * FD
                               + kc * 16 + ((lane >> 3) & 1) * 8));
                    uint32_t b0[2] = { r0, r1 }, b1[2] = { r2, r3 };
                    mma_f16(sa[2*njp],   a, b0);
                    mma_f16(sa[2*njp+1], a, b1);
                }
            }
        }

        // causal mask (last two kv tiles of this q tile)
        if (CAUSAL && kt >= 2 * qt) {
            int rowg = qt * 128 + wid * 16 + g;   // rows rowg and rowg+8
            #pragma unroll
            for (int nj = 0; nj < 8; nj++) {
                int colg = kt * 64 + nj * 8 + 2 * tq;
                if (colg     > rowg)     sa[nj][0] = -1e30f;
                if (colg + 1 > rowg)     sa[nj][1] = -1e30f;
                if (colg     > rowg + 8) sa[nj][2] = -1e30f;
                if (colg + 1 > rowg + 8) sa[nj][3] = -1e30f;
            }
        }

        float mx0 = -1e30f, mx1 = -1e30f;
        #pragma unroll
        for (int nj = 0; nj < 8; nj++) {
            mx0 = fmaxf(mx0, fmaxf(sa[nj][0], sa[nj][1]));
            mx1 = fmaxf(mx1, fmaxf(sa[nj][2], sa[nj][3]));
        }
        #pragma unroll
        for (int o = 1; o <= 2; o <<= 1) {
            mx0 = fmaxf(mx0, __shfl_xor_sync(0xffffffffu, mx0, o));
            mx1 = fmaxf(mx1, __shfl_xor_sync(0xffffffffu, mx1, o));
        }
        float mn0 = fmaxf(m0, mx0), mn1 = fmaxf(m1, mx1);
        float tm0 = mn0 * L2E, tm1 = mn1 * L2E;
        float corr0 = exp2f(m0 * L2E - tm0);
        float corr1 = exp2f(m1 * L2E - tm1);
        m0 = mn0; m1 = mn1;
        #pragma unroll
        for (int n = 0; n < 9; n++) {
            oa[n][0] *= corr0; oa[n][1] *= corr0;
            oa[n][2] *= corr1; oa[n][3] *= corr1;
        }
        uint32_t pf[8][2];
        #pragma unroll
        for (int nj = 0; nj < 8; nj++) {
            pf[nj][0] = ex2_f16x2(fmaf(sa[nj][0], L2E, -tm0), fmaf(sa[nj][1], L2E, -tm0));
            pf[nj][1] = ex2_f16x2(fmaf(sa[nj][2], L2E, -tm1), fmaf(sa[nj][3], L2E, -tm1));
        }

        // O += P V ; ones-column accumulates l
        {
            const __half* Vt = sV(s);
            #pragma unroll
            for (int kc = 0; kc < 4; kc++) {
                uint32_t a[4] = { pf[2*kc][0], pf[2*kc][1], pf[2*kc+1][0], pf[2*kc+1][1] };
                #pragma unroll
                for (int njp = 0; njp < 4; njp++) {
                    uint32_t r0, r1, r2, r3;
                    ldm_x4_t(r0, r1, r2, r3,
                        (uint32_t)__cvta_generic_to_shared(
                            Vt + (kc * 16 + ((lane >> 3) & 1) * 8 + (lane & 7)) * FD
                               + njp * 16 + ((lane >> 4) & 1) * 8));
                    uint32_t b0[2] = { r0, r1 }, b1[2] = { r2, r3 };
                    mma_f16(oa[2*njp],   a, b0);
                    mma_f16(oa[2*njp+1], a, b1);
                }
                uint32_t r0, r1;
                ldm_x2_t(r0, r1,
                    (uint32_t)__cvta_generic_to_shared(
                        Vt + (kc * 16 + (lane & 15)) * FD + 64));
                uint32_t b2[2] = { r0, r1 };
                mma_f16(oa[8], a, b2);
            }
        }

        __syncthreads();
        if (kt + 2 < ntiles) load_kv(s, kt + 2);
        asm volatile("cp.async.commit_group;\n" ::);
    }

    float l0 = __shfl_sync(0xffffffffu, oa[8][0], lane & ~3);
    float l1 = __shfl_sync(0xffffffffu, oa[8][2], lane & ~3);
    float inv0 = 1.0f / l0, inv1 = 1.0f / l1;

    size_t r0 = (size_t)b * T_SEQ + qt * 128 + wid * 16 + g;
    size_t r1 = r0 + 8;
    #pragma unroll
    for (int nj = 0; nj < 8; nj++) {
        int col = h * 64 + nj * 8 + 2 * tq;
        *(__half2*)(Op + r0 * C_DIM + col) =
            __floats2half2_rn(oa[nj][0] * inv0, oa[nj][1] * inv0);
        *(__half2*)(Op + r1 * C_DIM + col) =
            __floats2half2_rn(oa[nj][2] * inv1, oa[nj][3] * inv1);
    }
}

// ---------------------------------------------------------------------------
// Launch: R12-proven fork-join schedule (kv GEMM waits for fmha_self).
// ---------------------------------------------------------------------------
static inline int cdiv(int a, int b) { return (a + b - 1) / b; }

extern "C" void kernel_launch(void* const* d_in, const int* in_sizes, int n_in,
                              void* d_out, int out_size)
{
    const float* x           = (const float*)d_in[0];
    const float* context     = (const float*)d_in[1];
    const float* ln1_g       = (const float*)d_in[2];
    const float* ln1_b       = (const float*)d_in[3];
    const float* qkv_w       = (const float*)d_in[4];
    const float* qkv_b       = (const float*)d_in[5];
    const float* attn_out_w  = (const float*)d_in[6];
    const float* attn_out_b  = (const float*)d_in[7];
    const float* lnc_g       = (const float*)d_in[8];
    const float* lnc_b       = (const float*)d_in[9];
    const float* q_w         = (const float*)d_in[10];
    const float* q_b         = (const float*)d_in[11];
    const float* kv_w        = (const float*)d_in[12];
    const float* kv_b        = (const float*)d_in[13];
    const float* cross_out_w = (const float*)d_in[14];
    const float* cross_out_b = (const float*)d_in[15];
    const float* ln2_g       = (const float*)d_in[16];
    const float* ln2_b       = (const float*)d_in[17];
    const float* ffn_w1      = (const float*)d_in[18];
    const float* ffn_b1      = (const float*)d_in[19];
    const float* ffn_w2      = (const float*)d_in[20];
    const float* ffn_b2      = (const float*)d_in[21];
    float* out = (float*)d_out;

    float *x1, *x2;
    __half *h2, *attn2, *ctx2, *ffn2a;
    __half *wqkv2, *wao2, *wq2, *wkv2, *wco2, *wf1, *wf2;
    __half *qh, *kh, *vh;
    cudaGetSymbolAddress((void**)&x1,    g_x1);
    cudaGetSymbolAddress((void**)&x2,    g_x2);
    cudaGetSymbolAddress((void**)&h2,    g_h2);
    cudaGetSymbolAddress((void**)&attn2, g_attn2);
    cudaGetSymbolAddress((void**)&ctx2,  g_ctx2);
    cudaGetSymbolAddress((void**)&ffn2a, g_ffn2a);
    cudaGetSymbolAddress((void**)&wqkv2, w_qkv2);
    cudaGetSymbolAddress((void**)&wao2,  w_ao2);
    cudaGetSymbolAddress((void**)&wq2,   w_q2);
    cudaGetSymbolAddress((void**)&wkv2,  w_kv2);
    cudaGetSymbolAddress((void**)&wco2,  w_co2);
    cudaGetSymbolAddress((void**)&wf1,   w_f1_2);
    cudaGetSymbolAddress((void**)&wf2,   w_f2_2);
    cudaGetSymbolAddress((void**)&qh, a_qh);
    cudaGetSymbolAddress((void**)&kh, a_kh);
    cudaGetSymbolAddress((void**)&vh, a_vh);

    cudaFuncSetAttribute(bgemm_kernel<1>, cudaFuncAttributeMaxDynamicSharedMemorySize, BG_SMEM);
    cudaFuncSetAttribute(bgemm_kernel<3>, cudaFuncAttributeMaxDynamicSharedMemorySize, BG_SMEM);
    cudaFuncSetAttribute(bgemm_kernel<4>, cudaFuncAttributeMaxDynamicSharedMemorySize, BG_SMEM);
    cudaFuncSetAttribute(bgemm_kernel<5>, cudaFuncAttributeMaxDynamicSharedMemorySize, BG_SMEM);
    cudaFuncSetAttribute(bgemm_kernel<6>, cudaFuncAttributeMaxDynamicSharedMemorySize, BG_SMEM);
    cudaFuncSetAttribute(fmha_kernel<true>,  cudaFuncAttributeMaxDynamicSharedMemorySize, FMHA_SMEM);
    cudaFuncSetAttribute(fmha_kernel<false>, cudaFuncAttributeMaxDynamicSharedMemorySize, FMHA_SMEM);

    const int M = M_ROWS, C = C_DIM, F = F_DIM;
    dim3 fgrid(T_SEQ / 128, H_HEADS, 4);

    // --- fork-join infrastructure (leaked; kernel_launch runs only ~3x) ---
    cudaStream_t sB;
    cudaStreamCreateWithFlags(&sB, cudaStreamNonBlocking);
    cudaEvent_t evFork, evWqkv, evConvs, evSelf, evKV;
    cudaEventCreateWithFlags(&evFork,  cudaEventDisableTiming);
    cudaEventCreateWithFlags(&evWqkv,  cudaEventDisableTiming);
    cudaEventCreateWithFlags(&evConvs, cudaEventDisableTiming);
    cudaEventCreateWithFlags(&evSelf,  cudaEventDisableTiming);
    cudaEventCreateWithFlags(&evKV,    cudaEventDisableTiming);

    // fork
    cudaEventRecord(evFork, 0);
    cudaStreamWaitEvent(sB, evFork, 0);

    // Stream B: conversions (wqkv first so the qkv GEMM can start ASAP)
    convB_kernel<<<cdiv(C * 3 * C / 8, 256), 256, 0, sB>>>(qkv_w, wqkv2, C * 3 * C / 8);
    cudaEventRecord(evWqkv, sB);
    convB_kernel<<<cdiv(C * C / 8,     256), 256, 0, sB>>>(attn_out_w,  wao2, C * C / 8);
    convB_kernel<<<cdiv(C * C / 8,     256), 256, 0, sB>>>(q_w,         wq2,  C * C / 8);
    convB_kernel<<<cdiv(C * 2 * C / 8, 256), 256, 0, sB>>>(kv_w,        wkv2, C * 2 * C / 8);
    convB_kernel<<<cdiv(M * C / 8,     256), 256, 0, sB>>>(context,     ctx2, M * C / 8);
    convB_kernel<<<cdiv(C * C / 8,     256), 256, 0, sB>>>(cross_out_w, wco2, C * C / 8);
    convB_kernel<<<cdiv(C * F / 8,     256), 256, 0, sB>>>(ffn_w1,      wf1,  C * F / 8);
    convB_kernel<<<cdiv(F * C / 8,     256), 256, 0, sB>>>(ffn_w2,      wf2,  F * C / 8);
    cudaEventRecord(evConvs, sB);

    // Stream A (default): LN1, qkv GEMM (after wqkv2), self-attention
    ln_kernel<<<M, 256>>>(x, ln1_g, ln1_b, h2);
    cudaStreamWaitEvent(0, evWqkv, 0);
    bgemm_kernel<4><<<dim3(3 * C / BN, M / BM), 128, BG_SMEM>>>(
        h2, wqkv2, qkv_b, nullptr, nullptr, nullptr,
        qh, kh, vh, M, 3 * C, C);
    fmha_kernel<true><<<fgrid, 256, FMHA_SMEM>>>(qh, kh, vh, attn2);
    cudaEventRecord(evSelf, 0);

    // Stream B: kv GEMM (waits for fmha_self — it overwrites kh/vh)
    cudaStreamWaitEvent(sB, evSelf, 0);
    bgemm_kernel<6><<<dim3(2 * C / BN, M / BM), 128, BG_SMEM, sB>>>(
        ctx2, wkv2, kv_b, nullptr, nullptr, nullptr,
        nullptr, kh, vh, M, 2 * C, C);
    cudaEventRecord(evKV, sB);

    // Stream A: attn_out (needs wao2 -> evConvs), LNc, q GEMM
    cudaStreamWaitEvent(0, evConvs, 0);
    bgemm_kernel<1><<<dim3(C / BN, M / BM), 128, BG_SMEM>>>(
        attn2, wao2, attn_out_b, x, x1, nullptr,
        nullptr, nullptr, nullptr, M, C, C);
    ln_kernel<<<M, 256>>>(x1, lnc_g, lnc_b, h2);
    bgemm_kernel<5><<<dim3(C / BN, M / BM), 128, BG_SMEM>>>(
        h2, wq2, q_b, nullptr, nullptr, nullptr,
        qh, nullptr, nullptr, M, C, C);

    // join: cross-attention needs kv GEMM output
    cudaStreamWaitEvent(0, evKV, 0);
    fmha_kernel<false><<<fgrid, 256, FMHA_SMEM>>>(qh, kh, vh, attn2);
    bgemm_kernel<1><<<dim3(C / BN, M / BM), 128, BG_SMEM>>>(
        attn2, wco2, cross_out_b, x1, x2, nullptr,
        nullptr, nullptr, nullptr, M, C, C);

    // FFN
    ln_kernel<<<M, 256>>>(x2, ln2_g, ln2_b, h2);
    bgemm_kernel<3><<<dim3(F / BN, M / BM), 128, BG_SMEM>>>(
        h2, wf1, ffn_b1, nullptr, nullptr, ffn2a,
        nullptr, nullptr, nullptr, M, F, C);
    bgemm_kernel<1><<<dim3(C / BN, M / BM), 128, BG_SMEM>>>(
        ffn2a, wf2, ffn_b2, x2, out, nullptr,
        nullptr, nullptr, nullptr, M, C, F);
}

// round 17
// speedup vs baseline: 1.0451x; 1.0238x over previous
#include <cuda_runtime.h>
#include <cuda_bf16.h>
#include <cuda_fp16.h>
#include <cstdint>
#include <math.h>

// ---------------------------------------------------------------------------
// Problem constants: B=4, T=1024, C=1024, H=16, D=64, F=4096, M=B*T=4096
// ---------------------------------------------------------------------------
#define M_ROWS 4096
#define C_DIM  1024
#define T_SEQ  1024
#define H_HEADS 16
#define F_DIM  4096
#define L2E 1.4426950408889634f

// ---------------------------------------------------------------------------
// Scratch (device globals)
// ---------------------------------------------------------------------------
__device__ float g_x1 [M_ROWS * C_DIM];
__device__ float g_x2 [M_ROWS * C_DIM];

__device__ __half g_h2   [M_ROWS * C_DIM];
__device__ __half g_attn2[M_ROWS * C_DIM];
__device__ __half g_ctx2 [M_ROWS * C_DIM];
__device__ __half g_ffn2a[(size_t)M_ROWS * F_DIM];

__device__ __half w_qkv2[C_DIM * 3 * C_DIM];
__device__ __half w_ao2 [C_DIM * C_DIM];
__device__ __half w_q2  [C_DIM * C_DIM];
__device__ __half w_kv2 [C_DIM * 2 * C_DIM];
__device__ __half w_co2 [C_DIM * C_DIM];
__device__ __half w_f1_2[C_DIM * F_DIM];
__device__ __half w_f2_2[(size_t)F_DIM * C_DIM];

#define ATT_ELEMS (4 * H_HEADS * T_SEQ * 64)
__device__ __half a_qh[ATT_ELEMS];
__device__ __half a_kh[ATT_ELEMS];
__device__ __half a_vh[ATT_ELEMS];

// ---------------------------------------------------------------------------
// Helpers
// ---------------------------------------------------------------------------
__device__ __forceinline__ void cp16(uint32_t dst, const void* src) {
    asm volatile("cp.async.cg.shared.global [%0], [%1], 16;\n" :: "r"(dst), "l"(src));
}
__device__ __forceinline__ void ldm_x4(uint32_t& r0, uint32_t& r1, uint32_t& r2,
                                       uint32_t& r3, uint32_t addr) {
    asm volatile("ldmatrix.sync.aligned.m8n8.x4.shared.b16 {%0,%1,%2,%3}, [%4];\n"
        : "=r"(r0), "=r"(r1), "=r"(r2), "=r"(r3) : "r"(addr));
}
__device__ __forceinline__ void ldm_x4_t(uint32_t& r0, uint32_t& r1, uint32_t& r2,
                                         uint32_t& r3, uint32_t addr) {
    asm volatile("ldmatrix.sync.aligned.m8n8.x4.trans.shared.b16 {%0,%1,%2,%3}, [%4];\n"
        : "=r"(r0), "=r"(r1), "=r"(r2), "=r"(r3) : "r"(addr));
}
__device__ __forceinline__ void ldm_x2_t(uint32_t& r0, uint32_t& r1, uint32_t addr) {
    asm volatile("ldmatrix.sync.aligned.m8n8.x2.trans.shared.b16 {%0,%1}, [%2];\n"
        : "=r"(r0), "=r"(r1) : "r"(addr));
}
__device__ __forceinline__ void mma_f16(float* d, const uint32_t* a, const uint32_t* b) {
    asm volatile("mma.sync.aligned.m16n8k16.row.col.f32.f16.f16.f32 "
        "{%0,%1,%2,%3}, {%4,%5,%6,%7}, {%8,%9}, {%0,%1,%2,%3};\n"
        : "+f"(d[0]), "+f"(d[1]), "+f"(d[2]), "+f"(d[3])
        : "r"(a[0]), "r"(a[1]), "r"(a[2]), "r"(a[3]), "r"(b[0]), "r"(b[1]));
}
__device__ __forceinline__ uint32_t ex2_f16x2(float a, float b) {
    __half2 h = __floats2half2_rn(a, b);
    uint32_t u = *reinterpret_cast<uint32_t*>(&h);
    uint32_t r;
    asm volatile("ex2.approx.f16x2 %0, %1;\n" : "=r"(r) : "r"(u));
    return r;
}

// ---------------------------------------------------------------------------
// Vectorized conversion: fp32 -> f16, 8 elems/thread
// ---------------------------------------------------------------------------
__global__ void convB_kernel(const float* __restrict__ src, __half* __restrict__ dst,
                             int total8) {
    int e = blockIdx.x * 256 + threadIdx.x;
    if (e >= total8) return;
    const float4* s = (const float4*)src + 2 * (size_t)e;
    float4 a = s[0], b = s[1];
    __half2 h0 = __floats2half2_rn(a.x, a.y);
    __half2 h1 = __floats2half2_rn(a.z, a.w);
    __half2 h2 = __floats2half2_rn(b.x, b.y);
    __half2 h3 = __floats2half2_rn(b.z, b.w);
    uint4 pk = make_uint4(*(uint32_t*)&h0, *(uint32_t*)&h1,
                          *(uint32_t*)&h2, *(uint32_t*)&h3);
    ((uint4*)dst)[e] = pk;
}

// ---------------------------------------------------------------------------
// LayerNorm (writes f16)
// ---------------------------------------------------------------------------
__global__ void __launch_bounds__(256) ln_kernel(
    const float* __restrict__ x, const float* __restrict__ g,
    const float* __restrict__ b, __half* __restrict__ out)
{
    int row = blockIdx.x;
    int tid = threadIdx.x;
    float4 v = ((const float4*)(x + (size_t)row * C_DIM))[tid];
    float s  = v.x + v.y + v.z + v.w;
    float s2 = v.x*v.x + v.y*v.y + v.z*v.z + v.w*v.w;
    __shared__ float red[64];
    #pragma unroll
    for (int o = 16; o; o >>= 1) {
        s  += __shfl_xor_sync(0xffffffffu, s,  o);
        s2 += __shfl_xor_sync(0xffffffffu, s2, o);
    }
    int warp = tid >> 5;
    if ((tid & 31) == 0) { red[warp] = s; red[32 + warp] = s2; }
    __syncthreads();
    if (tid < 32) {
        s  = (tid < 8) ? red[tid]      : 0.f;
        s2 = (tid < 8) ? red[32 + tid] : 0.f;
        #pragma unroll
        for (int o = 4; o; o >>= 1) {
            s  += __shfl_xor_sync(0xffffffffu, s,  o);
            s2 += __shfl_xor_sync(0xffffffffu, s2, o);
        }
        if (tid == 0) { red[0] = s; red[32] = s2; }
    }
    __syncthreads();
    float mean = red[0]  * (1.0f / C_DIM);
    float var  = red[32] * (1.0f / C_DIM) - mean * mean;
    float inv  = rsqrtf(var + 1e-5f);
    float4 gv = ((const float4*)g)[tid];
    float4 bv = ((const float4*)b)[tid];
    __half2 o0 = __floats2half2_rn((v.x - mean) * inv * gv.x + bv.x,
                                   (v.y - mean) * inv * gv.y + bv.y);
    __half2 o1 = __floats2half2_rn((v.z - mean) * inv * gv.z + bv.z,
                                   (v.w - mean) * inv * gv.w + bv.w);
    uint2 pk = make_uint2(*(uint32_t*)&o0, *(uint32_t*)&o1);
    *(uint2*)(out + (size_t)row * C_DIM + 4 * tid) = pk;
}

// ---------------------------------------------------------------------------
// f16 tensor-core GEMM (exact R12-proven: 4-stage, single sync, 2 CTAs/SM)
// EPI: 1 = +bias+res (fp32 out)
//      3 = +bias, exact GELU, f16 out
//      4 = +bias, fused QKV attention-operand output
//      5 = +bias, q-only attention output (x0.125 -> f16)
//      6 = +bias, kv attention output (k | v)
// ---------------------------------------------------------------------------
#define BM 128
#define BN 128
#define BK 32
#define A_PAD 40
#define B_PAD 136
#define NSTAGE 4
#define BG_SMEM (NSTAGE * (BM * A_PAD + BK * B_PAD) * 2)   // 75776 B

template<int EPI>
__global__ void __launch_bounds__(128, 2) bgemm_kernel(
    const __half* __restrict__ A, const __half* __restrict__ Bm,
    const float* __restrict__ bias, const float* __restrict__ res,
    float* __restrict__ Cf, __half* __restrict__ Ct,
    __half* __restrict__ pq, __half* __restrict__ pkh,
    __half* __restrict__ pv,
    int M, int N, int Kp)
{
    extern __shared__ char sm_raw[];
    __half* As = (__half*)sm_raw;
    __half* Bs = (__half*)(sm_raw + NSTAGE * BM * A_PAD * sizeof(__half));

    const int tid  = threadIdx.x;
    const int lane = tid & 31, wid = tid >> 5;
    const int bm0 = blockIdx.y * BM, bn0 = blockIdx.x * BN;
    const int wm = (wid & 1) * 64, wn = (wid >> 1) * 64;

    float acc[4][8][4];
    #pragma unroll
    for (int i = 0; i < 4; i++)
        #pragma unroll
        for (int j = 0; j < 8; j++)
            #pragma unroll
            for (int r = 0; r < 4; r++) acc[i][j][r] = 0.f;

    auto As_u32 = [&](int s, int r, int c) -> uint32_t {
        return (uint32_t)__cvta_generic_to_shared(As + ((s * BM + r) * A_PAD + c));
    };
    auto Bs_u32 = [&](int s, int r, int c) -> uint32_t {
        return (uint32_t)__cvta_generic_to_shared(Bs + ((s * BK + r) * B_PAD + c));
    };

    auto load_stage = [&](int s, int k0) {
        #pragma unroll
        for (int i = 0; i < 4; i++) {
            int chunk = tid + i * 128;
            int ar = chunk >> 2, ac = (chunk & 3) * 8;
            cp16(As_u32(s, ar, ac), A + (size_t)(bm0 + ar) * Kp + k0 + ac);
            int br = chunk >> 4, bc = (chunk & 15) * 8;
            cp16(Bs_u32(s, br, bc), Bm + (size_t)(k0 + br) * N + bn0 + bc);
        }
        asm volatile("cp.async.commit_group;\n" ::);
    };

    const int NK = Kp / BK;
    load_stage(0, 0);
    load_stage(1, BK);
    load_stage(2, 2 * BK);

    for (int t = 0; t < NK; t++) {
        const int rem = NK - 1 - t;
        if (rem >= 2)      asm volatile("cp.async.wait_group 2;\n" ::);
        else if (rem == 1) asm volatile("cp.async.wait_group 1;\n" ::);
        else               asm volatile("cp.async.wait_group 0;\n" ::);
        __syncthreads();
        if (t + 3 < NK) load_stage((t + 3) & 3, (t + 3) * BK);
        const int s = t & 3;

        #pragma unroll
        for (int k16 = 0; k16 < 2; k16++) {
            uint32_t af[4][4];
            #pragma unroll
            for (int mi = 0; mi < 4; mi++) {
                uint32_t addr = As_u32(s, wm + mi * 16 + (lane & 15),
                                       k16 * 16 + ((lane >> 4) << 3));
                ldm_x4(af[mi][0], af[mi][1], af[mi][2], af[mi][3], addr);
            }
            uint32_t bfr[8][2];
            #pragma unroll
            for (int njp = 0; njp < 4; njp++) {
                int kr = k16 * 16 + ((lane >> 3) & 1) * 8 + (lane & 7);
                int nc = wn + njp * 16 + ((lane >> 4) & 1) * 8;
                uint32_t r0, r1, r2, r3;
                ldm_x4_t(r0, r1, r2, r3, Bs_u32(s, kr, nc));
                bfr[2*njp][0] = r0; bfr[2*njp][1] = r1;
                bfr[2*njp+1][0] = r2; bfr[2*njp+1][1] = r3;
            }
            #pragma unroll
            for (int mi = 0; mi < 4; mi++)
                #pragma unroll
                for (int nj = 0; nj < 8; nj++)
                    mma_f16(acc[mi][nj], af[mi], bfr[nj]);
        }
    }

    const int g = lane >> 2, tig = lane & 3;
    #pragma unroll
    for (int mi = 0; mi < 4; mi++) {
        #pragma unroll
        for (int r2 = 0; r2 < 2; r2++) {
            int row = bm0 + wm + mi * 16 + g + r2 * 8;
            #pragma unroll
            for (int nj = 0; nj < 8; nj++) {
                int col = bn0 + wn + nj * 8 + tig * 2;
                float v0 = acc[mi][nj][r2 * 2 + 0] + bias[col];
                float v1 = acc[mi][nj][r2 * 2 + 1] + bias[col + 1];
                if (EPI == 1) {
                    float2 rv = *(const float2*)(res + (size_t)row * N + col);
                    v0 += rv.x; v1 += rv.y;
                    *(float2*)(Cf + (size_t)row * N + col) = make_float2(v0, v1);
                }
                if (EPI == 3) {
                    v0 = 0.5f * v0 * (1.0f + erff(v0 * 0.7071067811865475f));
                    v1 = 0.5f * v1 * (1.0f + erff(v1 * 0.7071067811865475f));
                    *(__half2*)(Ct + (size_t)row * N + col) = __floats2half2_rn(v0, v1);
                }
                if (EPI >= 4) {
                    int kind = (EPI == 5) ? 0
                             : (EPI == 4) ? (col >> 10)
                             : ((col >> 10) + 1);
                    int cc = (EPI == 5) ? col : (col & 1023);
                    int hh = cc >> 6, dd = cc & 63;
                    int b_ = row >> 10, t_ = row & 1023;
                    size_t oidx = ((size_t)((b_ * 16 + hh) * 1024) + t_) * 64 + dd;
                    if (kind == 0) {
                        *(__half2*)(pq + oidx) =
                            __floats2half2_rn(v0 * 0.125f, v1 * 0.125f);
                    } else if (kind == 1) {
                        *(__half2*)(pkh + oidx) = __floats2half2_rn(v0, v1);
                    } else {
                        *(__half2*)(pv + oidx) = __floats2half2_rn(v0, v1);
                    }
                }
            }
        }
    }
}

// ---------------------------------------------------------------------------
// Tensor-core flash attention v3.1 (R12 geometry, BQ=64, 128 threads,
// 46 KB smem -> 4 CTAs/SM) with loop-invariant Q fragments hoisted into
// registers (loaded once at kt==0 instead of 4x ldmatrix per kv tile).
// ---------------------------------------------------------------------------
#define FD 72
#define FTILE (64 * FD)
#define FMHA_SMEM (5 * FTILE * 2)     // Q + 2 stages x (K, V)

template<bool CAUSAL>
__global__ void __launch_bounds__(128) fmha_kernel(
    const __half* __restrict__ Qh_, const __half* __restrict__ Kh_,
    const __half* __restrict__ Vh_, __half* __restrict__ Op)
{
    const int qt = CAUSAL ? (gridDim.x - 1 - (int)blockIdx.x) : blockIdx.x;
    const int h = blockIdx.y, b = blockIdx.z;
    const int bh = b * H_HEADS + h;
    const int tid = threadIdx.x;
    const int lane = tid & 31, wid = tid >> 5;

    extern __shared__ __half sm[];
    __half* sQ = sm;
    auto sK = [&](int s) { return sm + FTILE + (s * 2) * FTILE; };
    auto sV = [&](int s) { return sm + FTILE + (s * 2 + 1) * FTILE; };

    const size_t qbase  = ((size_t)bh * T_SEQ + qt * 64) * 64;
    const size_t kvbase = (size_t)bh * T_SEQ * 64;

    const int ntiles = CAUSAL ? (qt + 1) : (T_SEQ / 64);

    for (int idx = tid; idx < 64 * 8; idx += 128) {
        int pos = idx >> 3, c = 64 + (idx & 7);
        sV(0)[pos * FD + c] = (c == 64) ? __float2half(1.0f) : __float2half(0.0f);
        sV(1)[pos * FD + c] = (c == 64) ? __float2half(1.0f) : __float2half(0.0f);
    }

    auto load_q = [&]() {
        #pragma unroll
        for (int i = 0; i < 4; i++) {
            int chunk = tid + i * 128;
            int r = chunk >> 3, c8 = (chunk & 7) * 8;
            cp16((uint32_t)__cvta_generic_to_shared(sQ + r * FD + c8), Qh_ + qbase + r * 64 + c8);
        }
    };
    auto load_kv = [&](int s, int kt) {
        #pragma unroll
        for (int i = 0; i < 4; i++) {
            int chunk = tid + i * 128;
            int r = chunk >> 3, c8 = (chunk & 7) * 8;
            size_t src = kvbase + (size_t)(kt * 64 + r) * 64 + c8;
            cp16((uint32_t)__cvta_generic_to_shared(sK(s) + r * FD + c8), Kh_ + src);
            cp16((uint32_t)__cvta_generic_to_shared(sV(s) + r * FD + c8), Vh_ + src);
        }
    };

    load_q();
    load_kv(0, 0);
    asm volatile("cp.async.commit_group;\n" ::);
    if (ntiles > 1) load_kv(1, 1);
    asm volatile("cp.async.commit_group;\n" ::);

    float oa[9][4];
    #pragma unroll
    for (int n = 0; n < 9; n++)
        #pragma unroll
        for (int r = 0; r < 4; r++) oa[n][r] = 0.f;
    float m0 = -1e30f, m1 = -1e30f;

    uint32_t qf[4][4];   // loop-invariant Q fragments (filled at kt==0)

    const int g = lane >> 2, tq = lane & 3;

    for (int kt = 0; kt < ntiles; kt++) {
        const int s = kt & 1;
        if (kt + 1 < ntiles) asm volatile("cp.async.wait_group 1;\n" ::);
        else                 asm volatile("cp.async.wait_group 0;\n" ::);
        __syncthreads();

        if (kt == 0) {
            #pragma unroll
            for (int kc = 0; kc < 4; kc++)
                ldm_x4(qf[kc][0], qf[kc][1], qf[kc][2], qf[kc][3],
                    (uint32_t)__cvta_generic_to_shared(
                        sQ + (wid * 16 + (lane & 15)) * FD + kc * 16 + ((lane >> 4) << 3)));
        }

        float sa[8][4];
        #pragma unroll
        for (int n = 0; n < 8; n++)
            #pragma unroll
            for (int r = 0; r < 4; r++) sa[n][r] = 0.f;

        // S = Q * K (single pass, Q fragments in registers)
        {
            const __half* Kp = sK(s);
            #pragma unroll
            for (int kc = 0; kc < 4; kc++) {
                #pragma unroll
                for (int njp = 0; njp < 4; njp++) {
                    uint32_t r0, r1, r2, r3;
                    ldm_x4(r0, r1, r2, r3,
                        (uint32_t)__cvta_generic_to_shared(
                            Kp + (njp * 16 + ((lane >> 4) & 1) * 8 + (lane & 7)) * FD
                               + kc * 16 + ((lane >> 3) & 1) * 8));
                    uint32_t b0[2] = { r0, r1 }, b1[2] = { r2, r3 };
                    mma_f16(sa[2*njp],   qf[kc], b0);
                    mma_f16(sa[2*njp+1], qf[kc], b1);
                }
            }
        }

        if (CAUSAL && kt == qt) {
            int q0l = wid * 16 + g;
            #pragma unroll
            for (int nj = 0; nj < 8; nj++) {
                int c0 = nj * 8 + 2 * tq;
                if (c0     > q0l)     sa[nj][0] = -1e30f;
                if (c0 + 1 > q0l)     sa[nj][1] = -1e30f;
                if (c0     > q0l + 8) sa[nj][2] = -1e30f;
                if (c0 + 1 > q0l + 8) sa[nj][3] = -1e30f;
            }
        }

        float mx0 = -1e30f, mx1 = -1e30f;
        #pragma unroll
        for (int nj = 0; nj < 8; nj++) {
            mx0 = fmaxf(mx0, fmaxf(sa[nj][0], sa[nj][1]));
            mx1 = fmaxf(mx1, fmaxf(sa[nj][2], sa[nj][3]));
        }
        #pragma unroll
        for (int o = 1; o <= 2; o <<= 1) {
            mx0 = fmaxf(mx0, __shfl_xor_sync(0xffffffffu, mx0, o));
            mx1 = fmaxf(mx1, __shfl_xor_sync(0xffffffffu, mx1, o));
        }
        float mn0 = fmaxf(m0, mx0), mn1 = fmaxf(m1, mx1);
        float tm0 = mn0 * L2E, tm1 = mn1 * L2E;
        float corr0 = exp2f(m0 * L2E - tm0);
        float corr1 = exp2f(m1 * L2E - tm1);
        m0 = mn0; m1 = mn1;
        #pragma unroll
        for (int n = 0; n < 9; n++) {
            oa[n][0] *= corr0; oa[n][1] *= corr0;
            oa[n][2] *= corr1; oa[n][3] *= corr1;
        }
        uint32_t pf[8][2];
        #pragma unroll
        for (int nj = 0; nj < 8; nj++) {
            pf[nj][0] = ex2_f16x2(fmaf(sa[nj][0], L2E, -tm0), fmaf(sa[nj][1], L2E, -tm0));
            pf[nj][1] = ex2_f16x2(fmaf(sa[nj][2], L2E, -tm1), fmaf(sa[nj][3], L2E, -tm1));
        }

        // O += P V ; ones-column accumulates l
        {
            const __half* Vt = sV(s);
            #pragma unroll
            for (int kc = 0; kc < 4; kc++) {
                uint32_t a[4] = { pf[2*kc][0], pf[2*kc][1], pf[2*kc+1][0], pf[2*kc+1][1] };
                #pragma unroll
                for (int njp = 0; njp < 4; njp++) {
                    uint32_t r0, r1, r2, r3;
                    ldm_x4_t(r0, r1, r2, r3,
                        (uint32_t)__cvta_generic_to_shared(
                            Vt + (kc * 16 + ((lane >> 3) & 1) * 8 + (lane & 7)) * FD
                               + njp * 16 + ((lane >> 4) & 1) * 8));
                    uint32_t b0[2] = { r0, r1 }, b1[2] = { r2, r3 };
                    mma_f16(oa[2*njp],   a, b0);
                    mma_f16(oa[2*njp+1], a, b1);
                }
                uint32_t r0, r1;
                ldm_x2_t(r0, r1,
                    (uint32_t)__cvta_generic_to_shared(
                        Vt + (kc * 16 + (lane & 15)) * FD + 64));
                uint32_t b2[2] = { r0, r1 };
                mma_f16(oa[8], a, b2);
            }
        }

        __syncthreads();
        if (kt + 2 < ntiles) load_kv(s, kt + 2);
        asm volatile("cp.async.commit_group;\n" ::);
    }

    float l0 = __shfl_sync(0xffffffffu, oa[8][0], lane & ~3);
    float l1 = __shfl_sync(0xffffffffu, oa[8][2], lane & ~3);
    float inv0 = 1.0f / l0, inv1 = 1.0f / l1;

    size_t r0 = (size_t)b * T_SEQ + qt * 64 + wid * 16 + g;
    size_t r1 = r0 + 8;
    #pragma unroll
    for (int nj = 0; nj < 8; nj++) {
        int col = h * 64 + nj * 8 + 2 * tq;
        *(__half2*)(Op + r0 * C_DIM + col) =
            __floats2half2_rn(oa[nj][0] * inv0, oa[nj][1] * inv0);
        *(__half2*)(Op + r1 * C_DIM + col) =
            __floats2half2_rn(oa[nj][2] * inv1, oa[nj][3] * inv1);
    }
}

// ---------------------------------------------------------------------------
// Launch: R12-proven fork-join schedule (kv GEMM waits for fmha_self).
// ---------------------------------------------------------------------------
static inline int cdiv(int a, int b) { return (a + b - 1) / b; }

extern "C" void kernel_launch(void* const* d_in, const int* in_sizes, int n_in,
                              void* d_out, int out_size)
{
    const float* x           = (const float*)d_in[0];
    const float* context     = (const float*)d_in[1];
    const float* ln1_g       = (const float*)d_in[2];
    const float* ln1_b       = (const float*)d_in[3];
    const float* qkv_w       = (const float*)d_in[4];
    const float* qkv_b       = (const float*)d_in[5];
    const float* attn_out_w  = (const float*)d_in[6];
    const float* attn_out_b  = (const float*)d_in[7];
    const float* lnc_g       = (const float*)d_in[8];
    const float* lnc_b       = (const float*)d_in[9];
    const float* q_w         = (const float*)d_in[10];
    const float* q_b         = (const float*)d_in[11];
    const float* kv_w        = (const float*)d_in[12];
    const float* kv_b        = (const float*)d_in[13];
    const float* cross_out_w = (const float*)d_in[14];
    const float* cross_out_b = (const float*)d_in[15];
    const float* ln2_g       = (const float*)d_in[16];
    const float* ln2_b       = (const float*)d_in[17];
    const float* ffn_w1      = (const float*)d_in[18];
    const float* ffn_b1      = (const float*)d_in[19];
    const float* ffn_w2      = (const float*)d_in[20];
    const float* ffn_b2      = (const float*)d_in[21];
    float* out = (float*)d_out;

    float *x1, *x2;
    __half *h2, *attn2, *ctx2, *ffn2a;
    __half *wqkv2, *wao2, *wq2, *wkv2, *wco2, *wf1, *wf2;
    __half *qh, *kh, *vh;
    cudaGetSymbolAddress((void**)&x1,    g_x1);
    cudaGetSymbolAddress((void**)&x2,    g_x2);
    cudaGetSymbolAddress((void**)&h2,    g_h2);
    cudaGetSymbolAddress((void**)&attn2, g_attn2);
    cudaGetSymbolAddress((void**)&ctx2,  g_ctx2);
    cudaGetSymbolAddress((void**)&ffn2a, g_ffn2a);
    cudaGetSymbolAddress((void**)&wqkv2, w_qkv2);
    cudaGetSymbolAddress((void**)&wao2,  w_ao2);
    cudaGetSymbolAddress((void**)&wq2,   w_q2);
    cudaGetSymbolAddress((void**)&wkv2,  w_kv2);
    cudaGetSymbolAddress((void**)&wco2,  w_co2);
    cudaGetSymbolAddress((void**)&wf1,   w_f1_2);
    cudaGetSymbolAddress((void**)&wf2,   w_f2_2);
    cudaGetSymbolAddress((void**)&qh, a_qh);
    cudaGetSymbolAddress((void**)&kh, a_kh);
    cudaGetSymbolAddress((void**)&vh, a_vh);

    cudaFuncSetAttribute(bgemm_kernel<1>, cudaFuncAttributeMaxDynamicSharedMemorySize, BG_SMEM);
    cudaFuncSetAttribute(bgemm_kernel<3>, cudaFuncAttributeMaxDynamicSharedMemorySize, BG_SMEM);
    cudaFuncSetAttribute(bgemm_kernel<4>, cudaFuncAttributeMaxDynamicSharedMemorySize, BG_SMEM);
    cudaFuncSetAttribute(bgemm_kernel<5>, cudaFuncAttributeMaxDynamicSharedMemorySize, BG_SMEM);
    cudaFuncSetAttribute(bgemm_kernel<6>, cudaFuncAttributeMaxDynamicSharedMemorySize, BG_SMEM);
    cudaFuncSetAttribute(fmha_kernel<true>,  cudaFuncAttributeMaxDynamicSharedMemorySize, FMHA_SMEM);
    cudaFuncSetAttribute(fmha_kernel<false>, cudaFuncAttributeMaxDynamicSharedMemorySize, FMHA_SMEM);

    const int M = M_ROWS, C = C_DIM, F = F_DIM;
    dim3 fgrid(T_SEQ / 64, H_HEADS, 4);

    // --- fork-join infrastructure (leaked; kernel_launch runs only ~3x) ---
    cudaStream_t sB;
    cudaStreamCreateWithFlags(&sB, cudaStreamNonBlocking);
    cudaEvent_t evFork, evWqkv, evConvs, evSelf, evKV;
    cudaEventCreateWithFlags(&evFork,  cudaEventDisableTiming);
    cudaEventCreateWithFlags(&evWqkv,  cudaEventDisableTiming);
    cudaEventCreateWithFlags(&evConvs, cudaEventDisableTiming);
    cudaEventCreateWithFlags(&evSelf,  cudaEventDisableTiming);
    cudaEventCreateWithFlags(&evKV,    cudaEventDisableTiming);

    // fork
    cudaEventRecord(evFork, 0);
    cudaStreamWaitEvent(sB, evFork, 0);

    // Stream B: conversions (wqkv first so the qkv GEMM can start ASAP)
    convB_kernel<<<cdiv(C * 3 * C / 8, 256), 256, 0, sB>>>(qkv_w, wqkv2, C * 3 * C / 8);
    cudaEventRecord(evWqkv, sB);
    convB_kernel<<<cdiv(C * C / 8,     256), 256, 0, sB>>>(attn_out_w,  wao2, C * C / 8);
    convB_kernel<<<cdiv(C * C / 8,     256), 256, 0, sB>>>(q_w,         wq2,  C * C / 8);
    convB_kernel<<<cdiv(C * 2 * C / 8, 256), 256, 0, sB>>>(kv_w,        wkv2, C * 2 * C / 8);
    convB_kernel<<<cdiv(M * C / 8,     256), 256, 0, sB>>>(context,     ctx2, M * C / 8);
    convB_kernel<<<cdiv(C * C / 8,     256), 256, 0, sB>>>(cross_out_w, wco2, C * C / 8);
    convB_kernel<<<cdiv(C * F / 8,     256), 256, 0, sB>>>(ffn_w1,      wf1,  C * F / 8);
    convB_kernel<<<cdiv(F * C / 8,     256), 256, 0, sB>>>(ffn_w2,      wf2,  F * C / 8);
    cudaEventRecord(evConvs, sB);

    // Stream A (default): LN1, qkv GEMM (after wqkv2), self-attention
    ln_kernel<<<M, 256>>>(x, ln1_g, ln1_b, h2);
    cudaStreamWaitEvent(0, evWqkv, 0);
    bgemm_kernel<4><<<dim3(3 * C / BN, M / BM), 128, BG_SMEM>>>(
        h2, wqkv2, qkv_b, nullptr, nullptr, nullptr,
        qh, kh, vh, M, 3 * C, C);
    fmha_kernel<true><<<fgrid, 128, FMHA_SMEM>>>(qh, kh, vh, attn2);
    cudaEventRecord(evSelf, 0);

    // Stream B: kv GEMM (waits for fmha_self — it overwrites kh/vh)
    cudaStreamWaitEvent(sB, evSelf, 0);
    bgemm_kernel<6><<<dim3(2 * C / BN, M / BM), 128, BG_SMEM, sB>>>(
        ctx2, wkv2, kv_b, nullptr, nullptr, nullptr,
        nullptr, kh, vh, M, 2 * C, C);
    cudaEventRecord(evKV, sB);

    // Stream A: attn_out (needs wao2 -> evConvs), LNc, q GEMM
    cudaStreamWaitEvent(0, evConvs, 0);
    bgemm_kernel<1><<<dim3(C / BN, M / BM), 128, BG_SMEM>>>(
        attn2, wao2, attn_out_b, x, x1, nullptr,
        nullptr, nullptr, nullptr, M, C, C);
    ln_kernel<<<M, 256>>>(x1, lnc_g, lnc_b, h2);
    bgemm_kernel<5><<<dim3(C / BN, M / BM), 128, BG_SMEM>>>(
        h2, wq2, q_b, nullptr, nullptr, nullptr,
        qh, nullptr, nullptr, M, C, C);

    // join: cross-attention needs kv GEMM output
    cudaStreamWaitEvent(0, evKV, 0);
    fmha_kernel<false><<<fgrid, 128, FMHA_SMEM>>>(qh, kh, vh, attn2);
    bgemm_kernel<1><<<dim3(C / BN, M / BM), 128, BG_SMEM>>>(
        attn2, wco2, cross_out_b, x1, x2, nullptr,
        nullptr, nullptr, nullptr, M, C, C);

    // FFN
    ln_kernel<<<M, 256>>>(x2, ln2_g, ln2_b, h2);
    bgemm_kernel<3><<<dim3(F / BN, M / BM), 128, BG_SMEM>>>(
        h2, wf1, ffn_b1, nullptr, nullptr, ffn2a,
        nullptr, nullptr, nullptr, M, F, C);
    bgemm_kernel<1><<<dim3(C / BN, M / BM), 128, BG_SMEM>>>(
        ffn2a, wf2, ffn_b2, x2, out, nullptr,
        nullptr, nullptr, nullptr, M, C, F);
}